// round 13
// baseline (speedup 1.0000x reference)
#include <cuda_runtime.h>
#include <cuda_fp16.h>
#include <cuda_bf16.h>
#include <math.h>
#include <cstdint>

// Problem constants
#define Bdim 8
#define Nn   4096
#define Mm   4096
#define Cc   256

#define INV_EPS 33.333333333333336f           // 1/0.03
#define POWER   0.94339622641509435f          // 0.5/(0.5+0.03)
#define PROB    0.000244140625f               // 1/4096

// K rescale: Ks = 2^41 * K  (exact power-of-two scaling)
#define LN_SCALE  28.41903440295776f          // 41*ln(2)
#define PROB_S    536870912.0f                // PROB * 2^41 = 2^29
#define REG_S     21990.23255552f             // 1e-8 * 2^41
#define INV_SCALE 4.547473508864641e-13f      // 2^-41

// Packed operand: [0:256)=hi, [256:512)=hi(f1)/lo(f2), [512:768)=lo(f1)/hi(f2)
#define KPACK 768

// ---------------------------------------------------------------------------
// Static device scratch (no dynamic allocation allowed)
// ---------------------------------------------------------------------------
__device__ __nv_bfloat16 g_f1p[(size_t)Bdim * Nn * KPACK];    // 50.3 MB
__device__ __nv_bfloat16 g_f2p[(size_t)Bdim * Mm * KPACK];    // 50.3 MB
__device__ __half g_K[(size_t)Bdim * Nn * Mm];                // 268 MB (scaled 2^41)
__device__ float g_b[Bdim * Mm];
__device__ float g_part[(size_t)Bdim * 16 * Mm];              // init colsum partials (2MB)
__device__ float g_part2[(size_t)Bdim * 128 * Mm];            // fused colsum partials (17MB)
__device__ float g_w[Bdim * Nn];
__device__ float g_corr[Bdim * Nn * 3];

__device__ __forceinline__ float warp_sum(float v) {
#pragma unroll
    for (int o = 16; o; o >>= 1) v += __shfl_xor_sync(0xffffffffu, v, o);
    return v;
}

__device__ __forceinline__ uint32_t smem_u32(const void* p) {
    uint32_t a;
    asm("{ .reg .u64 t; cvta.to.shared.u64 t, %1; cvt.u32.u64 %0, t; }"
        : "=r"(a) : "l"(p));
    return a;
}

// SW128 swizzle: byte_off = row*128 + seg*16  ->  row*128 + (seg*16 ^ ((row&7)*16))
#define SWZ128(x) ((x) ^ (((x) >> 3) & 0x70))

// ---------------------------------------------------------------------------
// mma.sync / ldmatrix / cp.async helpers (baseline PTX, NOT arch-gated)
// ---------------------------------------------------------------------------
__device__ __forceinline__ void ldsm_x4(uint32_t* r, uint32_t addr) {
    asm volatile("ldmatrix.sync.aligned.m8n8.x4.shared.b16 {%0,%1,%2,%3}, [%4];"
                 : "=r"(r[0]), "=r"(r[1]), "=r"(r[2]), "=r"(r[3]) : "r"(addr));
}
__device__ __forceinline__ void mma_bf16(float* d, const uint32_t* a,
                                         uint32_t b0, uint32_t b1) {
    asm volatile(
        "mma.sync.aligned.m16n8k16.row.col.f32.bf16.bf16.f32 "
        "{%0,%1,%2,%3}, {%4,%5,%6,%7}, {%8,%9}, {%0,%1,%2,%3};"
        : "+f"(d[0]), "+f"(d[1]), "+f"(d[2]), "+f"(d[3])
        : "r"(a[0]), "r"(a[1]), "r"(a[2]), "r"(a[3]), "r"(b0), "r"(b1));
}
__device__ __forceinline__ void cp_async16(uint32_t smem_dst, const void* gsrc) {
    asm volatile("cp.async.cg.shared.global [%0], [%1], 16;"
                 :: "r"(smem_dst), "l"(gsrc));
}
#define CP_COMMIT()  asm volatile("cp.async.commit_group;" ::: "memory")
#define CP_WAIT(N)   asm volatile("cp.async.wait_group %0;" :: "n"(N) : "memory")

// ---------------------------------------------------------------------------
// 1. L2-normalize + bf16 hi/lo split-pack (one warp per 256-float row)
//    f1 row: [hi | hi | lo];  f2 row: [hi | lo | hi]
// ---------------------------------------------------------------------------
__device__ __forceinline__ void pack_store(__nv_bfloat16* dst, int e, float4 v, int which) {
    float vv[4] = {v.x, v.y, v.z, v.w};
    __nv_bfloat16 hi[4], lo[4];
#pragma unroll
    for (int i = 0; i < 4; i++) {
        hi[i] = __float2bfloat16(vv[i]);
        lo[i] = __float2bfloat16(vv[i] - __bfloat162float(hi[i]));
    }
    __nv_bfloat162 h01, h23, l01, l23;
    h01.x = hi[0]; h01.y = hi[1]; h23.x = hi[2]; h23.y = hi[3];
    l01.x = lo[0]; l01.y = lo[1]; l23.x = lo[2]; l23.y = lo[3];
    *reinterpret_cast<__nv_bfloat162*>(dst + e)     = h01;
    *reinterpret_cast<__nv_bfloat162*>(dst + e + 2) = h23;
    if (which == 0) {
        *reinterpret_cast<__nv_bfloat162*>(dst + 256 + e)     = h01;
        *reinterpret_cast<__nv_bfloat162*>(dst + 256 + e + 2) = h23;
        *reinterpret_cast<__nv_bfloat162*>(dst + 512 + e)     = l01;
        *reinterpret_cast<__nv_bfloat162*>(dst + 512 + e + 2) = l23;
    } else {
        *reinterpret_cast<__nv_bfloat162*>(dst + 256 + e)     = l01;
        *reinterpret_cast<__nv_bfloat162*>(dst + 256 + e + 2) = l23;
        *reinterpret_cast<__nv_bfloat162*>(dst + 512 + e)     = h01;
        *reinterpret_cast<__nv_bfloat162*>(dst + 512 + e + 2) = h23;
    }
}

__global__ void uot_norm_pack_kernel(const float* __restrict__ src, int which) {
    int gw   = (blockIdx.x * blockDim.x + threadIdx.x) >> 5;
    int lane = threadIdx.x & 31;
    if (gw >= Bdim * Nn) return;

    const float4* s4 = reinterpret_cast<const float4*>(src) + (size_t)gw * 64;
    float4 v0 = s4[lane];
    float4 v1 = s4[lane + 32];
    float ss = v0.x*v0.x + v0.y*v0.y + v0.z*v0.z + v0.w*v0.w
             + v1.x*v1.x + v1.y*v1.y + v1.z*v1.z + v1.w*v1.w;
    ss = warp_sum(ss);
    float inv = 1.0f / sqrtf(ss + 1e-8f);
    v0.x *= inv; v0.y *= inv; v0.z *= inv; v0.w *= inv;
    v1.x *= inv; v1.y *= inv; v1.z *= inv; v1.w *= inv;

    __nv_bfloat16* dst = (which ? g_f2p : g_f1p) + (size_t)gw * KPACK;
    int e = lane * 4;
    pack_store(dst, e, v0, which);
    pack_store(dst, e + 128, v1, which);
}

// ---------------------------------------------------------------------------
// 2. HMMA GEMM: Ks = 2^41*exp((f1.f2-1)/eps), fp16 store. (unchanged, works)
// ---------------------------------------------------------------------------
#define STAGE_BYTES 16384                 // 128 rows x 128 B
#define BUF_BYTES   32768                 // A + B per stage
#define SMEM_DYN    98304                 // 3 bufs

__global__ __launch_bounds__(256) void uot_mma_exp_kernel() {
    extern __shared__ char smem[];
    uint32_t sb = smem_u32(smem);
    int tid  = threadIdx.x;
    int wid  = tid >> 5;
    int lane = tid & 31;

    int bz = blockIdx.z;
    int r0 = blockIdx.y * 128;     // output rows  (f1 index)
    int c0 = blockIdx.x * 128;     // output cols  (f2 index)

    const char* Abase = reinterpret_cast<const char*>(
        g_f1p + ((size_t)bz * Nn + r0) * KPACK);
    const char* Bbase = reinterpret_cast<const char*>(
        g_f2p + ((size_t)bz * Mm + c0) * KPACK);

    int segid[8];
#pragma unroll
    for (int i = 0; i < 8; i++) segid[i] = tid + i * 256;

    auto prefetch = [&](int st) {
        uint32_t base = sb + (uint32_t)(st % 3) * BUF_BYTES;
        const char* Asrc = Abase + st * 128;
        const char* Bsrc = Bbase + st * 128;
#pragma unroll
        for (int i = 0; i < 8; i++) {
            int l   = segid[i];
            int isB = l >> 10;
            int row = (l >> 3) & 127;
            int seg = l & 7;
            const char* src = (isB ? Bsrc : Asrc) + (size_t)row * (KPACK * 2) + seg * 16;
            uint32_t dst = base + isB * STAGE_BYTES + SWZ128(row * 128 + seg * 16);
            cp_async16(dst, src);
        }
    };

    int mt = (wid & 3) * 32;        // warp row offset (A side)
    int ntw = (wid >> 2) * 64;      // warp col offset (B side)

    int arow0 = mt + (lane & 15);
    int aks   = lane >> 4;
    uint32_t aoff0 = arow0 * 128;
    uint32_t axor0 = (uint32_t)((arow0 & 7) * 16);
    int arow1 = arow0 + 16;
    uint32_t aoff1 = arow1 * 128;
    uint32_t axor1 = (uint32_t)((arow1 & 7) * 16);

    int brow = ntw + ((lane & 7) | ((lane >> 1) & 8));
    int bks  = (lane >> 3) & 1;
    uint32_t boff = brow * 128;
    uint32_t bxor = (uint32_t)((brow & 7) * 16);

    float acc[2][8][4];
#pragma unroll
    for (int i = 0; i < 2; i++)
#pragma unroll
        for (int j = 0; j < 8; j++)
#pragma unroll
            for (int k = 0; k < 4; k++) acc[i][j][k] = 0.0f;

    prefetch(0); CP_COMMIT();
    prefetch(1); CP_COMMIT();

    for (int st = 0; st < 12; st++) {
        CP_WAIT(1);
        __syncthreads();
        if (st + 2 < 12) { prefetch(st + 2); CP_COMMIT(); }

        uint32_t baseA = sb + (uint32_t)(st % 3) * BUF_BYTES;
        uint32_t baseB = baseA + STAGE_BYTES;
#pragma unroll
        for (int kc = 0; kc < 4; kc++) {
            uint32_t kseg = (uint32_t)((kc * 2 + aks) * 16);
            uint32_t a0[4], a1[4];
            ldsm_x4(a0, baseA + aoff0 + (kseg ^ axor0));
            ldsm_x4(a1, baseA + aoff1 + (kseg ^ axor1));
            uint32_t kbseg = (uint32_t)((kc * 2 + bks) * 16);
#pragma unroll
            for (int nb = 0; nb < 4; nb++) {
                uint32_t bfrag[4];
                ldsm_x4(bfrag, baseB + boff + (uint32_t)(nb * 16 * 128) + (kbseg ^ bxor));
                mma_bf16(acc[0][2 * nb + 0], a0, bfrag[0], bfrag[1]);
                mma_bf16(acc[0][2 * nb + 1], a0, bfrag[2], bfrag[3]);
                mma_bf16(acc[1][2 * nb + 0], a1, bfrag[0], bfrag[1]);
                mma_bf16(acc[1][2 * nb + 1], a1, bfrag[2], bfrag[3]);
            }
        }
    }

    // --- Epilogue: exp -> fp16, direct register stores ---
    int g  = lane >> 2;
    int tg = lane & 3;
    __half* Kout = g_K + ((size_t)bz * Nn + r0) * Mm + c0;
#pragma unroll
    for (int mi = 0; mi < 2; mi++) {
        int rowA = mt + mi * 16 + g;
#pragma unroll
        for (int ni = 0; ni < 8; ni++) {
            int col = ntw + ni * 8 + tg * 2;
            float* d = acc[mi][ni];
            float e0 = fminf(__expf(fmaf(d[0] - 1.0f, INV_EPS, LN_SCALE)), 60000.0f);
            float e1 = fminf(__expf(fmaf(d[1] - 1.0f, INV_EPS, LN_SCALE)), 60000.0f);
            float e2 = fminf(__expf(fmaf(d[2] - 1.0f, INV_EPS, LN_SCALE)), 60000.0f);
            float e3 = fminf(__expf(fmaf(d[3] - 1.0f, INV_EPS, LN_SCALE)), 60000.0f);
            *reinterpret_cast<__half2*>(&Kout[(size_t)rowA * Mm + col]) =
                __floats2half2_rn(e0, e1);
            *reinterpret_cast<__half2*>(&Kout[(size_t)(rowA + 8) * Mm + col]) =
                __floats2half2_rn(e2, e3);
        }
    }
}

// ---------------------------------------------------------------------------
// 3. Initial column sums with a0 = 1/N (1024 blocks: 16 splits of 256 rows)
// ---------------------------------------------------------------------------
__global__ void uot_colsum_init_kernel() {
    int m2    = blockIdx.x * 256 + threadIdx.x;     // pair index 0..2047
    int split = blockIdx.y;                          // 0..15
    int b     = blockIdx.z;
    const __half2* Kp =
        reinterpret_cast<const __half2*>(
            g_K + ((size_t)b * Nn + (size_t)split * 256) * Mm) + m2;
    float s0x = 0.f, s0y = 0.f, s1x = 0.f, s1y = 0.f;
#pragma unroll 4
    for (int n = 0; n < 256; n += 2) {
        float2 k0 = __half22float2(Kp[(size_t)n * 2048]);
        float2 k1 = __half22float2(Kp[(size_t)(n + 1) * 2048]);
        s0x += k0.x; s0y += k0.y;
        s1x += k1.x; s1y += k1.y;
    }
    float* dst = g_part + (size_t)(b * 16 + split) * Mm + 2 * m2;
    dst[0] = (s0x + s1x) * PROB;
    dst[1] = (s0y + s1y) * PROB;
}

// ---------------------------------------------------------------------------
// 4. b = (prob2*S / (sum of 16 init partials + 1e-8*S)) ^ power
// ---------------------------------------------------------------------------
__global__ void uot_b_update_kernel() {
    int i = blockIdx.x * blockDim.x + threadIdx.x;
    if (i >= Bdim * Mm) return;
    int b = i >> 12;
    int m = i & 4095;
    const float* p = g_part + (size_t)(b * 16) * Mm + m;
    float s = 0.f;
#pragma unroll
    for (int j = 0; j < 16; j++) s += p[(size_t)j * Mm];
    g_b[i] = powf(PROB_S / (s + REG_S), POWER);
}

// ---------------------------------------------------------------------------
// 5. Fused Sinkhorn pass v3: single DRAM read per iteration, 32 rows/block.
//    Block owns rows rb*32..rb*32+31 as 4 sequential 8-row subtiles.
//    Per subtile: phase a = warp-per-row rowsum + stage row to smem;
//                 phase b = colsum accumulate from smem (conflict-free).
//    colacc registers persist across subtiles -> one partial row per block.
// ---------------------------------------------------------------------------
#define FUSED_ROWS 8
#define FUSED_SMEM (FUSED_ROWS * Mm * 2 + 64)     // 65600

__global__ __launch_bounds__(256) void uot_fused_kernel() {
    extern __shared__ char fsm[];
    __half* tile = reinterpret_cast<__half*>(fsm);                 // 8 x 4096 halves
    float*  sh_a = reinterpret_cast<float*>(fsm + FUSED_ROWS * Mm * 2);
    int tid  = threadIdx.x;
    int wid  = tid >> 5;
    int lane = tid & 31;
    int rb = blockIdx.x;               // 0..127
    int b  = blockIdx.y;               // 0..7
    const float4* bp = reinterpret_cast<const float4*>(g_b + b * Mm);

    float ca[16];
#pragma unroll
    for (int j = 0; j < 16; j++) ca[j] = 0.f;

    for (int t = 0; t < 4; t++) {
        int row0 = rb * 32 + t * FUSED_ROWS;
        const __half* Kbase = g_K + ((size_t)b * Nn + row0) * Mm;

        // phase a: warp wid handles row wid (stream from DRAM, dot + stage)
        {
            const uint4* Kp = reinterpret_cast<const uint4*>(Kbase + (size_t)wid * Mm);
            uint4* Tp = reinterpret_cast<uint4*>(tile + (size_t)wid * Mm);
            float acc = 0.f;
#pragma unroll 4
            for (int it = 0; it < 16; it++) {
                int idx = it * 32 + lane;
                uint4 u = Kp[idx];
                Tp[idx] = u;
                float2 f0 = __half22float2(*reinterpret_cast<__half2*>(&u.x));
                float2 f1 = __half22float2(*reinterpret_cast<__half2*>(&u.y));
                float2 f2 = __half22float2(*reinterpret_cast<__half2*>(&u.z));
                float2 f3 = __half22float2(*reinterpret_cast<__half2*>(&u.w));
                float4 b0 = __ldg(&bp[idx * 2]);
                float4 b1 = __ldg(&bp[idx * 2 + 1]);
                acc += f0.x * b0.x + f0.y * b0.y + f1.x * b0.z + f1.y * b0.w
                     + f2.x * b1.x + f2.y * b1.y + f3.x * b1.z + f3.y * b1.w;
            }
            acc = warp_sum(acc);
            if (lane == 0) sh_a[wid] = powf(PROB_S / (acc + REG_S), POWER);
        }
        __syncthreads();

        // phase b: thread owns 16B segments tid and tid+256 (cols seg*8..+7)
#pragma unroll
        for (int r = 0; r < FUSED_ROWS; r++) {
            const uint4* Tp = reinterpret_cast<const uint4*>(tile + (size_t)r * Mm);
            uint4 u0 = Tp[tid];
            uint4 u1 = Tp[tid + 256];
            float a = sh_a[r];
            float2 f;
            f = __half22float2(*reinterpret_cast<__half2*>(&u0.x)); ca[0]  = fmaf(a, f.x, ca[0]);  ca[1]  = fmaf(a, f.y, ca[1]);
            f = __half22float2(*reinterpret_cast<__half2*>(&u0.y)); ca[2]  = fmaf(a, f.x, ca[2]);  ca[3]  = fmaf(a, f.y, ca[3]);
            f = __half22float2(*reinterpret_cast<__half2*>(&u0.z)); ca[4]  = fmaf(a, f.x, ca[4]);  ca[5]  = fmaf(a, f.y, ca[5]);
            f = __half22float2(*reinterpret_cast<__half2*>(&u0.w)); ca[6]  = fmaf(a, f.x, ca[6]);  ca[7]  = fmaf(a, f.y, ca[7]);
            f = __half22float2(*reinterpret_cast<__half2*>(&u1.x)); ca[8]  = fmaf(a, f.x, ca[8]);  ca[9]  = fmaf(a, f.y, ca[9]);
            f = __half22float2(*reinterpret_cast<__half2*>(&u1.y)); ca[10] = fmaf(a, f.x, ca[10]); ca[11] = fmaf(a, f.y, ca[11]);
            f = __half22float2(*reinterpret_cast<__half2*>(&u1.z)); ca[12] = fmaf(a, f.x, ca[12]); ca[13] = fmaf(a, f.y, ca[13]);
            f = __half22float2(*reinterpret_cast<__half2*>(&u1.w)); ca[14] = fmaf(a, f.x, ca[14]); ca[15] = fmaf(a, f.y, ca[15]);
        }
        __syncthreads();   // protect tile before next subtile's phase a
    }

    float* prow = g_part2 + ((size_t)(b * 128 + rb)) * Mm;
    float4* d0 = reinterpret_cast<float4*>(prow + tid * 8);
    d0[0] = make_float4(ca[0], ca[1], ca[2],  ca[3]);
    d0[1] = make_float4(ca[4], ca[5], ca[6],  ca[7]);
    float4* d1 = reinterpret_cast<float4*>(prow + (tid + 256) * 8);
    d1[0] = make_float4(ca[8],  ca[9],  ca[10], ca[11]);
    d1[1] = make_float4(ca[12], ca[13], ca[14], ca[15]);
}

// ---------------------------------------------------------------------------
// 6. b-update from 128 fused partials (direct, no intermediate reduce)
// ---------------------------------------------------------------------------
__global__ void uot_b_update2_kernel() {
    int i = blockIdx.x * blockDim.x + threadIdx.x;
    if (i >= Bdim * Mm) return;
    int b = i >> 12;
    int m = i & 4095;
    const float* p = g_part2 + (size_t)b * 128 * Mm + m;
    float s0 = 0.f, s1 = 0.f, s2 = 0.f, s3 = 0.f;
#pragma unroll 4
    for (int rb = 0; rb < 128; rb += 4) {
        s0 += p[(size_t)(rb + 0) * Mm];
        s1 += p[(size_t)(rb + 1) * Mm];
        s2 += p[(size_t)(rb + 2) * Mm];
        s3 += p[(size_t)(rb + 3) * Mm];
    }
    g_b[i] = powf(PROB_S / ((s0 + s1) + (s2 + s3) + REG_S), POWER);
}

// ---------------------------------------------------------------------------
// 7. Final fused pass: Ks·b and Ks·(b*p2_{xyz}) -> a, w, corr
// ---------------------------------------------------------------------------
__global__ void uot_rowsum_final_kernel(const float* __restrict__ p2) {
    int gw   = (blockIdx.x * blockDim.x + threadIdx.x) >> 5;
    int lane = threadIdx.x & 31;
    if (gw >= Bdim * Nn) return;
    int b = gw >> 12;
    int n = gw & 4095;
    const uint4*  Kp  = reinterpret_cast<const uint4*>(g_K + ((size_t)b * Nn + n) * Mm);
    const float4* bp  = reinterpret_cast<const float4*>(g_b + b * Mm);
    const float*  p2b = p2 + (size_t)b * Mm * 3;

    float a0 = 0.f, ax = 0.f, ay = 0.f, az = 0.f;
    for (int it = 0; it < 16; it++) {
        int idx = it * 32 + lane;
        int m8  = idx * 8;
        uint4 u = Kp[idx];
        float kv[8];
        {
            float2 f0 = __half22float2(*reinterpret_cast<__half2*>(&u.x));
            float2 f1 = __half22float2(*reinterpret_cast<__half2*>(&u.y));
            float2 f2 = __half22float2(*reinterpret_cast<__half2*>(&u.z));
            float2 f3 = __half22float2(*reinterpret_cast<__half2*>(&u.w));
            kv[0] = f0.x; kv[1] = f0.y; kv[2] = f1.x; kv[3] = f1.y;
            kv[4] = f2.x; kv[5] = f2.y; kv[6] = f3.x; kv[7] = f3.y;
        }
        float bv[8];
        {
            float4 b0 = __ldg(&bp[idx * 2]);
            float4 b1 = __ldg(&bp[idx * 2 + 1]);
            bv[0] = b0.x; bv[1] = b0.y; bv[2] = b0.z; bv[3] = b0.w;
            bv[4] = b1.x; bv[5] = b1.y; bv[6] = b1.z; bv[7] = b1.w;
        }
        float pv[24];
        {
            const float4* q4 = reinterpret_cast<const float4*>(p2b + (size_t)m8 * 3);
#pragma unroll
            for (int t = 0; t < 6; t++) {
                float4 qq = __ldg(&q4[t]);
                pv[4 * t + 0] = qq.x; pv[4 * t + 1] = qq.y;
                pv[4 * t + 2] = qq.z; pv[4 * t + 3] = qq.w;
            }
        }
#pragma unroll
        for (int e = 0; e < 8; e++) {
            float t = kv[e] * bv[e];
            a0 += t;
            ax = fmaf(t, pv[e * 3 + 0], ax);
            ay = fmaf(t, pv[e * 3 + 1], ay);
            az = fmaf(t, pv[e * 3 + 2], az);
        }
    }
    a0 = warp_sum(a0);
    ax = warp_sum(ax);
    ay = warp_sum(ay);
    az = warp_sum(az);
    if (lane == 0) {
        float av  = powf(PROB_S / (a0 + REG_S), POWER);
        float kb  = a0 * INV_SCALE;
        float w   = av * kb;
        float inv = 1.0f / (w + 1e-8f);
        g_w[gw] = w;
        g_corr[(size_t)gw * 3 + 0] = av * (ax * INV_SCALE) * inv;
        g_corr[(size_t)gw * 3 + 1] = av * (ay * INV_SCALE) * inv;
        g_corr[(size_t)gw * 3 + 2] = av * (az * INV_SCALE) * inv;
    }
}

// ---------------------------------------------------------------------------
// 8. Weighted Kabsch, one block per batch. 3x3 SVD via Jacobi (double) on t0.
// ---------------------------------------------------------------------------
__global__ void uot_kabsch_kernel(const float* __restrict__ p1, float* __restrict__ out) {
    int b    = blockIdx.x;
    int tid  = threadIdx.x;
    int lane = tid & 31;
    int wid  = tid >> 5;

    __shared__ float red[8][16];
    __shared__ float sh[16];

    float v[7];
#pragma unroll
    for (int j = 0; j < 7; j++) v[j] = 0.f;
    for (int n = tid; n < Nn; n += 256) {
        float wv = g_w[b * Nn + n];
        const float* q1 = p1 + ((size_t)b * Nn + n) * 3;
        const float* qc = g_corr + ((size_t)b * Nn + n) * 3;
        v[0] += wv;
        v[1] += wv * q1[0]; v[2] += wv * q1[1]; v[3] += wv * q1[2];
        v[4] += wv * qc[0]; v[5] += wv * qc[1]; v[6] += wv * qc[2];
    }
#pragma unroll
    for (int j = 0; j < 7; j++) {
        float t = warp_sum(v[j]);
        if (lane == 0) red[wid][j] = t;
    }
    __syncthreads();
    if (tid < 7) {
        float t = 0.f;
        for (int w8 = 0; w8 < 8; w8++) t += red[w8][tid];
        sh[tid] = t;
    }
    __syncthreads();
    float denom = sh[0] + 1e-5f;
    float ca0 = sh[1] / denom, ca1 = sh[2] / denom, ca2 = sh[3] / denom;
    float cb0 = sh[4] / denom, cb1 = sh[5] / denom, cb2 = sh[6] / denom;
    __syncthreads();

    float c9[9];
#pragma unroll
    for (int j = 0; j < 9; j++) c9[j] = 0.f;
    for (int n = tid; n < Nn; n += 256) {
        float wn = g_w[b * Nn + n] / denom;
        const float* q1 = p1 + ((size_t)b * Nn + n) * 3;
        const float* qc = g_corr + ((size_t)b * Nn + n) * 3;
        float a0 = q1[0] - ca0, a1 = q1[1] - ca1, a2 = q1[2] - ca2;
        float e0 = (qc[0] - cb0) * wn, e1 = (qc[1] - cb1) * wn, e2 = (qc[2] - cb2) * wn;
        c9[0] += a0 * e0; c9[1] += a0 * e1; c9[2] += a0 * e2;
        c9[3] += a1 * e0; c9[4] += a1 * e1; c9[5] += a1 * e2;
        c9[6] += a2 * e0; c9[7] += a2 * e1; c9[8] += a2 * e2;
    }
#pragma unroll
    for (int j = 0; j < 9; j++) {
        float t = warp_sum(c9[j]);
        if (lane == 0) red[wid][j] = t;
    }
    __syncthreads();
    if (tid < 9) {
        float t = 0.f;
        for (int w8 = 0; w8 < 8; w8++) t += red[w8][tid];
        sh[tid] = t;
    }
    __syncthreads();

    if (tid == 0) {
        double Cv[3][3];
        for (int r = 0; r < 3; r++)
            for (int c = 0; c < 3; c++) Cv[r][c] = (double)sh[r * 3 + c];

        double S[3][3];
        for (int i = 0; i < 3; i++)
            for (int j = 0; j < 3; j++)
                S[i][j] = Cv[0][i] * Cv[0][j] + Cv[1][i] * Cv[1][j] + Cv[2][i] * Cv[2][j];

        double V[3][3] = {{1, 0, 0}, {0, 1, 0}, {0, 0, 1}};
        const int PQ[3][2] = {{0, 1}, {0, 2}, {1, 2}};
        for (int sweep = 0; sweep < 45; sweep++) {
            int p = PQ[sweep % 3][0], q = PQ[sweep % 3][1];
            double apq = S[p][q];
            if (fabs(apq) < 1e-60) continue;
            double tau = (S[q][q] - S[p][p]) / (2.0 * apq);
            double t   = ((tau >= 0.0) ? 1.0 : -1.0) / (fabs(tau) + sqrt(1.0 + tau * tau));
            double cc  = 1.0 / sqrt(1.0 + t * t);
            double ss  = t * cc;
            for (int k = 0; k < 3; k++) {
                double skp = S[k][p], skq = S[k][q];
                S[k][p] = cc * skp - ss * skq;
                S[k][q] = ss * skp + cc * skq;
            }
            for (int k = 0; k < 3; k++) {
                double spk = S[p][k], sqk = S[q][k];
                S[p][k] = cc * spk - ss * sqk;
                S[q][k] = ss * spk + cc * sqk;
            }
            for (int k = 0; k < 3; k++) {
                double vkp = V[k][p], vkq = V[k][q];
                V[k][p] = cc * vkp - ss * vkq;
                V[k][q] = ss * vkp + cc * vkq;
            }
        }

        double lam[3] = {S[0][0], S[1][1], S[2][2]};
        int idx[3] = {0, 1, 2};
        for (int i = 0; i < 2; i++)
            for (int j = i + 1; j < 3; j++)
                if (lam[idx[j]] > lam[idx[i]]) { int t = idx[i]; idx[i] = idx[j]; idx[j] = t; }

        double Vs[3][3];
        for (int r = 0; r < 3; r++)
            for (int i = 0; i < 3; i++) Vs[r][i] = V[r][idx[i]];

        double U[3][3];
        for (int i = 0; i < 3; i++)
            for (int r = 0; r < 3; r++)
                U[r][i] = Cv[r][0] * Vs[0][i] + Cv[r][1] * Vs[1][i] + Cv[r][2] * Vs[2][i];

        {
            double nrm = sqrt(U[0][0]*U[0][0] + U[1][0]*U[1][0] + U[2][0]*U[2][0]);
            double inv = (nrm > 1e-150) ? 1.0 / nrm : 0.0;
            for (int r = 0; r < 3; r++) U[r][0] *= inv;
        }
        {
            double d01 = U[0][0]*U[0][1] + U[1][0]*U[1][1] + U[2][0]*U[2][1];
            for (int r = 0; r < 3; r++) U[r][1] -= d01 * U[r][0];
            double nrm = sqrt(U[0][1]*U[0][1] + U[1][1]*U[1][1] + U[2][1]*U[2][1]);
            double inv = (nrm > 1e-150) ? 1.0 / nrm : 0.0;
            for (int r = 0; r < 3; r++) U[r][1] *= inv;
        }
        {
            double d02 = U[0][0]*U[0][2] + U[1][0]*U[1][2] + U[2][0]*U[2][2];
            double d12 = U[0][1]*U[0][2] + U[1][1]*U[1][2] + U[2][1]*U[2][2];
            for (int r = 0; r < 3; r++) U[r][2] -= d02 * U[r][0] + d12 * U[r][1];
            double nrm = sqrt(U[0][2]*U[0][2] + U[1][2]*U[1][2] + U[2][2]*U[2][2]);
            if (nrm > 1e-12) {
                for (int r = 0; r < 3; r++) U[r][2] /= nrm;
            } else {
                U[0][2] = U[1][0]*U[2][1] - U[2][0]*U[1][1];
                U[1][2] = U[2][0]*U[0][1] - U[0][0]*U[2][1];
                U[2][2] = U[0][0]*U[1][1] - U[1][0]*U[0][1];
            }
        }

        double R[3][3];
        for (int r = 0; r < 3; r++)
            for (int c = 0; c < 3; c++)
                R[r][c] = Vs[r][0]*U[c][0] + Vs[r][1]*U[c][1] + Vs[r][2]*U[c][2];
        double det = R[0][0]*(R[1][1]*R[2][2] - R[1][2]*R[2][1])
                   - R[0][1]*(R[1][0]*R[2][2] - R[1][2]*R[2][0])
                   + R[0][2]*(R[1][0]*R[2][1] - R[1][1]*R[2][0]);
        if (!(det > 0.0)) {
            for (int r = 0; r < 3; r++)
                for (int c = 0; c < 3; c++)
                    R[r][c] -= 2.0 * Vs[r][2] * U[c][2];
        }

        double cad[3] = {ca0, ca1, ca2};
        double cbd[3] = {cb0, cb1, cb2};
        for (int r = 0; r < 3; r++) {
            double tr = cbd[r] - (R[r][0]*cad[0] + R[r][1]*cad[1] + R[r][2]*cad[2]);
            out[b * 12 + r * 4 + 0] = (float)R[r][0];
            out[b * 12 + r * 4 + 1] = (float)R[r][1];
            out[b * 12 + r * 4 + 2] = (float)R[r][2];
            out[b * 12 + r * 4 + 3] = (float)tr;
        }
    }
}

// ---------------------------------------------------------------------------
// Launch
// ---------------------------------------------------------------------------
extern "C" void kernel_launch(void* const* d_in, const int* in_sizes, int n_in,
                              void* d_out, int out_size) {
    const float* f1 = (const float*)d_in[0];
    const float* f2 = (const float*)d_in[1];
    const float* p1 = (const float*)d_in[2];
    const float* p2 = (const float*)d_in[3];
    float* out = (float*)d_out;

    static bool attr_set = false;
    if (!attr_set) {
        cudaFuncSetAttribute(uot_mma_exp_kernel,
                             cudaFuncAttributeMaxDynamicSharedMemorySize, SMEM_DYN);
        cudaFuncSetAttribute(uot_fused_kernel,
                             cudaFuncAttributeMaxDynamicSharedMemorySize, FUSED_SMEM);
        attr_set = true;
    }

    uot_norm_pack_kernel<<<4096, 256>>>(f1, 0);
    uot_norm_pack_kernel<<<4096, 256>>>(f2, 1);
    uot_mma_exp_kernel<<<dim3(32, 32, Bdim), 256, SMEM_DYN>>>();

    // iteration 1: colsum(a0=1/N) -> b1
    uot_colsum_init_kernel<<<dim3(8, 16, Bdim), 256>>>();
    uot_b_update_kernel<<<(Bdim * Mm + 255) / 256, 256>>>();

    // iterations 1..9: fused rowsum->a_t (smem tile), colsum(a_t) -> b_{t+1}
    for (int it = 0; it < 9; ++it) {
        uot_fused_kernel<<<dim3(128, Bdim), 256, FUSED_SMEM>>>();
        uot_b_update2_kernel<<<(Bdim * Mm + 255) / 256, 256>>>();
    }

    // iteration 10's rowsum: a_10, w, corr (uses b_10)
    uot_rowsum_final_kernel<<<4096, 256>>>(p2);

    uot_kabsch_kernel<<<Bdim, 256>>>(p1, out);
}

// round 14
// speedup vs baseline: 1.0934x; 1.0934x over previous
#include <cuda_runtime.h>
#include <cuda_fp16.h>
#include <cuda_bf16.h>
#include <math.h>
#include <cstdint>

// Problem constants
#define Bdim 8
#define Nn   4096
#define Mm   4096
#define Cc   256

#define INV_EPS 33.333333333333336f           // 1/0.03
#define POWER   0.94339622641509435f          // 0.5/(0.5+0.03)
#define PROB    0.000244140625f               // 1/4096

// K rescale: Ks = 2^41 * K  (exact power-of-two scaling)
#define LN_SCALE  28.41903440295776f          // 41*ln(2)
#define PROB_S    536870912.0f                // PROB * 2^41 = 2^29
#define REG_S     21990.23255552f             // 1e-8 * 2^41
#define INV_SCALE 4.547473508864641e-13f      // 2^-41

// Packed operand: [0:256)=hi, [256:512)=hi(f1)/lo(f2), [512:768)=lo(f1)/hi(f2)
#define KPACK 768

// ---------------------------------------------------------------------------
// Static device scratch (no dynamic allocation allowed)
// ---------------------------------------------------------------------------
__device__ __nv_bfloat16 g_f1p[(size_t)Bdim * Nn * KPACK];    // 50.3 MB
__device__ __nv_bfloat16 g_f2p[(size_t)Bdim * Mm * KPACK];    // 50.3 MB
__device__ __half g_K[(size_t)Bdim * Nn * Mm];                // 268 MB (scaled 2^41)
__device__ float g_b[Bdim * Mm];
__device__ float g_part[(size_t)Bdim * 16 * Mm];              // init colsum partials (2MB)
__device__ float g_part2[(size_t)Bdim * 512 * Mm];            // fused colsum partials (67MB)
__device__ float g_w[Bdim * Nn];
__device__ float g_corr[Bdim * Nn * 3];

__device__ __forceinline__ float warp_sum(float v) {
#pragma unroll
    for (int o = 16; o; o >>= 1) v += __shfl_xor_sync(0xffffffffu, v, o);
    return v;
}

__device__ __forceinline__ uint32_t smem_u32(const void* p) {
    uint32_t a;
    asm("{ .reg .u64 t; cvta.to.shared.u64 t, %1; cvt.u32.u64 %0, t; }"
        : "=r"(a) : "l"(p));
    return a;
}

// SW128 swizzle: byte_off = row*128 + seg*16  ->  row*128 + (seg*16 ^ ((row&7)*16))
#define SWZ128(x) ((x) ^ (((x) >> 3) & 0x70))

// ---------------------------------------------------------------------------
// mma.sync / ldmatrix / cp.async helpers (baseline PTX, NOT arch-gated)
// ---------------------------------------------------------------------------
__device__ __forceinline__ void ldsm_x4(uint32_t* r, uint32_t addr) {
    asm volatile("ldmatrix.sync.aligned.m8n8.x4.shared.b16 {%0,%1,%2,%3}, [%4];"
                 : "=r"(r[0]), "=r"(r[1]), "=r"(r[2]), "=r"(r[3]) : "r"(addr));
}
__device__ __forceinline__ void mma_bf16(float* d, const uint32_t* a,
                                         uint32_t b0, uint32_t b1) {
    asm volatile(
        "mma.sync.aligned.m16n8k16.row.col.f32.bf16.bf16.f32 "
        "{%0,%1,%2,%3}, {%4,%5,%6,%7}, {%8,%9}, {%0,%1,%2,%3};"
        : "+f"(d[0]), "+f"(d[1]), "+f"(d[2]), "+f"(d[3])
        : "r"(a[0]), "r"(a[1]), "r"(a[2]), "r"(a[3]), "r"(b0), "r"(b1));
}
__device__ __forceinline__ void cp_async16(uint32_t smem_dst, const void* gsrc) {
    asm volatile("cp.async.cg.shared.global [%0], [%1], 16;"
                 :: "r"(smem_dst), "l"(gsrc));
}
#define CP_COMMIT()  asm volatile("cp.async.commit_group;" ::: "memory")
#define CP_WAIT(N)   asm volatile("cp.async.wait_group %0;" :: "n"(N) : "memory")

// ---------------------------------------------------------------------------
// 1. L2-normalize + bf16 hi/lo split-pack (one warp per 256-float row)
//    f1 row: [hi | hi | lo];  f2 row: [hi | lo | hi]
//    Merged kernel: blocks [0,4096) process f1, [4096,8192) process f2.
// ---------------------------------------------------------------------------
__device__ __forceinline__ void pack_store(__nv_bfloat16* dst, int e, float4 v, int which) {
    float vv[4] = {v.x, v.y, v.z, v.w};
    __nv_bfloat16 hi[4], lo[4];
#pragma unroll
    for (int i = 0; i < 4; i++) {
        hi[i] = __float2bfloat16(vv[i]);
        lo[i] = __float2bfloat16(vv[i] - __bfloat162float(hi[i]));
    }
    __nv_bfloat162 h01, h23, l01, l23;
    h01.x = hi[0]; h01.y = hi[1]; h23.x = hi[2]; h23.y = hi[3];
    l01.x = lo[0]; l01.y = lo[1]; l23.x = lo[2]; l23.y = lo[3];
    *reinterpret_cast<__nv_bfloat162*>(dst + e)     = h01;
    *reinterpret_cast<__nv_bfloat162*>(dst + e + 2) = h23;
    if (which == 0) {
        *reinterpret_cast<__nv_bfloat162*>(dst + 256 + e)     = h01;
        *reinterpret_cast<__nv_bfloat162*>(dst + 256 + e + 2) = h23;
        *reinterpret_cast<__nv_bfloat162*>(dst + 512 + e)     = l01;
        *reinterpret_cast<__nv_bfloat162*>(dst + 512 + e + 2) = l23;
    } else {
        *reinterpret_cast<__nv_bfloat162*>(dst + 256 + e)     = l01;
        *reinterpret_cast<__nv_bfloat162*>(dst + 256 + e + 2) = l23;
        *reinterpret_cast<__nv_bfloat162*>(dst + 512 + e)     = h01;
        *reinterpret_cast<__nv_bfloat162*>(dst + 512 + e + 2) = h23;
    }
}

__global__ void uot_norm_pack_kernel(const float* __restrict__ f1,
                                     const float* __restrict__ f2) {
    int gwa  = (blockIdx.x * blockDim.x + threadIdx.x) >> 5;   // 0..65535
    int lane = threadIdx.x & 31;
    int which = (gwa >= Bdim * Nn) ? 1 : 0;
    int gw = which ? (gwa - Bdim * Nn) : gwa;
    const float* src = which ? f2 : f1;

    const float4* s4 = reinterpret_cast<const float4*>(src) + (size_t)gw * 64;
    float4 v0 = s4[lane];
    float4 v1 = s4[lane + 32];
    float ss = v0.x*v0.x + v0.y*v0.y + v0.z*v0.z + v0.w*v0.w
             + v1.x*v1.x + v1.y*v1.y + v1.z*v1.z + v1.w*v1.w;
    ss = warp_sum(ss);
    float inv = 1.0f / sqrtf(ss + 1e-8f);
    v0.x *= inv; v0.y *= inv; v0.z *= inv; v0.w *= inv;
    v1.x *= inv; v1.y *= inv; v1.z *= inv; v1.w *= inv;

    __nv_bfloat16* dst = (which ? g_f2p : g_f1p) + (size_t)gw * KPACK;
    int e = lane * 4;
    pack_store(dst, e, v0, which);
    pack_store(dst, e + 128, v1, which);
}

// ---------------------------------------------------------------------------
// 2. HMMA GEMM: Ks = 2^41*exp((f1.f2-1)/eps), fp16 store. (unchanged, works)
// ---------------------------------------------------------------------------
#define STAGE_BYTES 16384                 // 128 rows x 128 B
#define BUF_BYTES   32768                 // A + B per stage
#define SMEM_DYN    98304                 // 3 bufs

__global__ __launch_bounds__(256) void uot_mma_exp_kernel() {
    extern __shared__ char smem[];
    uint32_t sb = smem_u32(smem);
    int tid  = threadIdx.x;
    int wid  = tid >> 5;
    int lane = tid & 31;

    int bz = blockIdx.z;
    int r0 = blockIdx.y * 128;     // output rows  (f1 index)
    int c0 = blockIdx.x * 128;     // output cols  (f2 index)

    const char* Abase = reinterpret_cast<const char*>(
        g_f1p + ((size_t)bz * Nn + r0) * KPACK);
    const char* Bbase = reinterpret_cast<const char*>(
        g_f2p + ((size_t)bz * Mm + c0) * KPACK);

    int segid[8];
#pragma unroll
    for (int i = 0; i < 8; i++) segid[i] = tid + i * 256;

    auto prefetch = [&](int st) {
        uint32_t base = sb + (uint32_t)(st % 3) * BUF_BYTES;
        const char* Asrc = Abase + st * 128;
        const char* Bsrc = Bbase + st * 128;
#pragma unroll
        for (int i = 0; i < 8; i++) {
            int l   = segid[i];
            int isB = l >> 10;
            int row = (l >> 3) & 127;
            int seg = l & 7;
            const char* src = (isB ? Bsrc : Asrc) + (size_t)row * (KPACK * 2) + seg * 16;
            uint32_t dst = base + isB * STAGE_BYTES + SWZ128(row * 128 + seg * 16);
            cp_async16(dst, src);
        }
    };

    int mt = (wid & 3) * 32;        // warp row offset (A side)
    int ntw = (wid >> 2) * 64;      // warp col offset (B side)

    int arow0 = mt + (lane & 15);
    int aks   = lane >> 4;
    uint32_t aoff0 = arow0 * 128;
    uint32_t axor0 = (uint32_t)((arow0 & 7) * 16);
    int arow1 = arow0 + 16;
    uint32_t aoff1 = arow1 * 128;
    uint32_t axor1 = (uint32_t)((arow1 & 7) * 16);

    int brow = ntw + ((lane & 7) | ((lane >> 1) & 8));
    int bks  = (lane >> 3) & 1;
    uint32_t boff = brow * 128;
    uint32_t bxor = (uint32_t)((brow & 7) * 16);

    float acc[2][8][4];
#pragma unroll
    for (int i = 0; i < 2; i++)
#pragma unroll
        for (int j = 0; j < 8; j++)
#pragma unroll
            for (int k = 0; k < 4; k++) acc[i][j][k] = 0.0f;

    prefetch(0); CP_COMMIT();
    prefetch(1); CP_COMMIT();

    for (int st = 0; st < 12; st++) {
        CP_WAIT(1);
        __syncthreads();
        if (st + 2 < 12) { prefetch(st + 2); CP_COMMIT(); }

        uint32_t baseA = sb + (uint32_t)(st % 3) * BUF_BYTES;
        uint32_t baseB = baseA + STAGE_BYTES;
#pragma unroll
        for (int kc = 0; kc < 4; kc++) {
            uint32_t kseg = (uint32_t)((kc * 2 + aks) * 16);
            uint32_t a0[4], a1[4];
            ldsm_x4(a0, baseA + aoff0 + (kseg ^ axor0));
            ldsm_x4(a1, baseA + aoff1 + (kseg ^ axor1));
            uint32_t kbseg = (uint32_t)((kc * 2 + bks) * 16);
#pragma unroll
            for (int nb = 0; nb < 4; nb++) {
                uint32_t bfrag[4];
                ldsm_x4(bfrag, baseB + boff + (uint32_t)(nb * 16 * 128) + (kbseg ^ bxor));
                mma_bf16(acc[0][2 * nb + 0], a0, bfrag[0], bfrag[1]);
                mma_bf16(acc[0][2 * nb + 1], a0, bfrag[2], bfrag[3]);
                mma_bf16(acc[1][2 * nb + 0], a1, bfrag[0], bfrag[1]);
                mma_bf16(acc[1][2 * nb + 1], a1, bfrag[2], bfrag[3]);
            }
        }
    }

    // --- Epilogue: exp -> fp16, direct register stores ---
    int g  = lane >> 2;
    int tg = lane & 3;
    __half* Kout = g_K + ((size_t)bz * Nn + r0) * Mm + c0;
#pragma unroll
    for (int mi = 0; mi < 2; mi++) {
        int rowA = mt + mi * 16 + g;
#pragma unroll
        for (int ni = 0; ni < 8; ni++) {
            int col = ntw + ni * 8 + tg * 2;
            float* d = acc[mi][ni];
            float e0 = fminf(__expf(fmaf(d[0] - 1.0f, INV_EPS, LN_SCALE)), 60000.0f);
            float e1 = fminf(__expf(fmaf(d[1] - 1.0f, INV_EPS, LN_SCALE)), 60000.0f);
            float e2 = fminf(__expf(fmaf(d[2] - 1.0f, INV_EPS, LN_SCALE)), 60000.0f);
            float e3 = fminf(__expf(fmaf(d[3] - 1.0f, INV_EPS, LN_SCALE)), 60000.0f);
            *reinterpret_cast<__half2*>(&Kout[(size_t)rowA * Mm + col]) =
                __floats2half2_rn(e0, e1);
            *reinterpret_cast<__half2*>(&Kout[(size_t)(rowA + 8) * Mm + col]) =
                __floats2half2_rn(e2, e3);
        }
    }
}

// ---------------------------------------------------------------------------
// 3. Initial column sums with a0 = 1/N (1024 blocks: 16 splits of 256 rows)
// ---------------------------------------------------------------------------
__global__ void uot_colsum_init_kernel() {
    int m2    = blockIdx.x * 256 + threadIdx.x;     // pair index 0..2047
    int split = blockIdx.y;                          // 0..15
    int b     = blockIdx.z;
    const __half2* Kp =
        reinterpret_cast<const __half2*>(
            g_K + ((size_t)b * Nn + (size_t)split * 256) * Mm) + m2;
    float s0x = 0.f, s0y = 0.f, s1x = 0.f, s1y = 0.f;
#pragma unroll 4
    for (int n = 0; n < 256; n += 2) {
        float2 k0 = __half22float2(Kp[(size_t)n * 2048]);
        float2 k1 = __half22float2(Kp[(size_t)(n + 1) * 2048]);
        s0x += k0.x; s0y += k0.y;
        s1x += k1.x; s1y += k1.y;
    }
    float* dst = g_part + (size_t)(b * 16 + split) * Mm + 2 * m2;
    dst[0] = (s0x + s1x) * PROB;
    dst[1] = (s0y + s1y) * PROB;
}

// ---------------------------------------------------------------------------
// 4. b = (prob2*S / (sum of 16 init partials + 1e-8*S)) ^ power
// ---------------------------------------------------------------------------
__global__ void uot_b_update_kernel() {
    int i = blockIdx.x * blockDim.x + threadIdx.x;
    if (i >= Bdim * Mm) return;
    int b = i >> 12;
    int m = i & 4095;
    const float* p = g_part + (size_t)(b * 16) * Mm + m;
    float s = 0.f;
#pragma unroll
    for (int j = 0; j < 16; j++) s += p[(size_t)j * Mm];
    g_b[i] = powf(PROB_S / (s + REG_S), POWER);
}

// ---------------------------------------------------------------------------
// 5. Fused Sinkhorn pass (v2, 4096 blocks — wave-safe): single DRAM read.
//    Block = 8 rows x 4096 cols. Phase a: warp-per-row rowsum + stage row to
//    smem. Phase b: colsum partials from smem (conflict-free).
//    65.6KB smem -> 3 CTAs/SM; 4096 blocks = ~9 waves (no tail problem).
// ---------------------------------------------------------------------------
#define FUSED_ROWS 8
#define FUSED_SMEM (FUSED_ROWS * Mm * 2 + 64)     // 65600

__global__ __launch_bounds__(256) void uot_fused_kernel() {
    extern __shared__ char fsm[];
    __half* tile = reinterpret_cast<__half*>(fsm);                 // 8 x 4096 halves
    float*  sh_a = reinterpret_cast<float*>(fsm + FUSED_ROWS * Mm * 2);
    int tid  = threadIdx.x;
    int wid  = tid >> 5;
    int lane = tid & 31;
    int rb = blockIdx.x;               // 0..511
    int b  = blockIdx.y;               // 0..7
    int row0 = rb * FUSED_ROWS;
    const __half* Kbase = g_K + ((size_t)b * Nn + row0) * Mm;
    const float4* bp = reinterpret_cast<const float4*>(g_b + b * Mm);

    // phase a: warp wid handles row wid (stream from DRAM, dot + stage)
    {
        const uint4* Kp = reinterpret_cast<const uint4*>(Kbase + (size_t)wid * Mm);
        uint4* Tp = reinterpret_cast<uint4*>(tile + (size_t)wid * Mm);
        float acc = 0.f;
#pragma unroll 4
        for (int it = 0; it < 16; it++) {
            int idx = it * 32 + lane;
            uint4 u = Kp[idx];
            Tp[idx] = u;
            float2 f0 = __half22float2(*reinterpret_cast<__half2*>(&u.x));
            float2 f1 = __half22float2(*reinterpret_cast<__half2*>(&u.y));
            float2 f2 = __half22float2(*reinterpret_cast<__half2*>(&u.z));
            float2 f3 = __half22float2(*reinterpret_cast<__half2*>(&u.w));
            float4 b0 = __ldg(&bp[idx * 2]);
            float4 b1 = __ldg(&bp[idx * 2 + 1]);
            acc += f0.x * b0.x + f0.y * b0.y + f1.x * b0.z + f1.y * b0.w
                 + f2.x * b1.x + f2.y * b1.y + f3.x * b1.z + f3.y * b1.w;
        }
        acc = warp_sum(acc);
        if (lane == 0) sh_a[wid] = powf(PROB_S / (acc + REG_S), POWER);
    }
    __syncthreads();

    float av[FUSED_ROWS];
#pragma unroll
    for (int r = 0; r < FUSED_ROWS; r++) av[r] = sh_a[r];

    // phase b: thread owns 16B segments tid and tid+256 (cols seg*8..+7)
    float ca[16];
#pragma unroll
    for (int j = 0; j < 16; j++) ca[j] = 0.f;
#pragma unroll
    for (int r = 0; r < FUSED_ROWS; r++) {
        const uint4* Tp = reinterpret_cast<const uint4*>(tile + (size_t)r * Mm);
        uint4 u0 = Tp[tid];
        uint4 u1 = Tp[tid + 256];
        float a = av[r];
        float2 f;
        f = __half22float2(*reinterpret_cast<__half2*>(&u0.x)); ca[0]  = fmaf(a, f.x, ca[0]);  ca[1]  = fmaf(a, f.y, ca[1]);
        f = __half22float2(*reinterpret_cast<__half2*>(&u0.y)); ca[2]  = fmaf(a, f.x, ca[2]);  ca[3]  = fmaf(a, f.y, ca[3]);
        f = __half22float2(*reinterpret_cast<__half2*>(&u0.z)); ca[4]  = fmaf(a, f.x, ca[4]);  ca[5]  = fmaf(a, f.y, ca[5]);
        f = __half22float2(*reinterpret_cast<__half2*>(&u0.w)); ca[6]  = fmaf(a, f.x, ca[6]);  ca[7]  = fmaf(a, f.y, ca[7]);
        f = __half22float2(*reinterpret_cast<__half2*>(&u1.x)); ca[8]  = fmaf(a, f.x, ca[8]);  ca[9]  = fmaf(a, f.y, ca[9]);
        f = __half22float2(*reinterpret_cast<__half2*>(&u1.y)); ca[10] = fmaf(a, f.x, ca[10]); ca[11] = fmaf(a, f.y, ca[11]);
        f = __half22float2(*reinterpret_cast<__half2*>(&u1.z)); ca[12] = fmaf(a, f.x, ca[12]); ca[13] = fmaf(a, f.y, ca[13]);
        f = __half22float2(*reinterpret_cast<__half2*>(&u1.w)); ca[14] = fmaf(a, f.x, ca[14]); ca[15] = fmaf(a, f.y, ca[15]);
    }
    float* prow = g_part2 + ((size_t)(b * 512 + rb)) * Mm;
    float4* d0 = reinterpret_cast<float4*>(prow + tid * 8);
    d0[0] = make_float4(ca[0], ca[1], ca[2],  ca[3]);
    d0[1] = make_float4(ca[4], ca[5], ca[6],  ca[7]);
    float4* d1 = reinterpret_cast<float4*>(prow + (tid + 256) * 8);
    d1[0] = make_float4(ca[8],  ca[9],  ca[10], ca[11]);
    d1[1] = make_float4(ca[12], ca[13], ca[14], ca[15]);
}

// ---------------------------------------------------------------------------
// 6. b-update directly from 512 fused partials (no intermediate reduce)
// ---------------------------------------------------------------------------
__global__ void uot_b_update2_kernel() {
    int i = blockIdx.x * blockDim.x + threadIdx.x;
    if (i >= Bdim * Mm) return;
    int b = i >> 12;
    int m = i & 4095;
    const float* p = g_part2 + (size_t)b * 512 * Mm + m;
    float s0 = 0.f, s1 = 0.f, s2 = 0.f, s3 = 0.f;
#pragma unroll 4
    for (int rb = 0; rb < 512; rb += 4) {
        s0 += p[(size_t)(rb + 0) * Mm];
        s1 += p[(size_t)(rb + 1) * Mm];
        s2 += p[(size_t)(rb + 2) * Mm];
        s3 += p[(size_t)(rb + 3) * Mm];
    }
    g_b[i] = powf(PROB_S / ((s0 + s1) + (s2 + s3) + REG_S), POWER);
}

// ---------------------------------------------------------------------------
// 7. Final fused pass: Ks·b and Ks·(b*p2_{xyz}) -> a, w, corr
// ---------------------------------------------------------------------------
__global__ void uot_rowsum_final_kernel(const float* __restrict__ p2) {
    int gw   = (blockIdx.x * blockDim.x + threadIdx.x) >> 5;
    int lane = threadIdx.x & 31;
    if (gw >= Bdim * Nn) return;
    int b = gw >> 12;
    int n = gw & 4095;
    const uint4*  Kp  = reinterpret_cast<const uint4*>(g_K + ((size_t)b * Nn + n) * Mm);
    const float4* bp  = reinterpret_cast<const float4*>(g_b + b * Mm);
    const float*  p2b = p2 + (size_t)b * Mm * 3;

    float a0 = 0.f, ax = 0.f, ay = 0.f, az = 0.f;
    for (int it = 0; it < 16; it++) {
        int idx = it * 32 + lane;
        int m8  = idx * 8;
        uint4 u = Kp[idx];
        float kv[8];
        {
            float2 f0 = __half22float2(*reinterpret_cast<__half2*>(&u.x));
            float2 f1 = __half22float2(*reinterpret_cast<__half2*>(&u.y));
            float2 f2 = __half22float2(*reinterpret_cast<__half2*>(&u.z));
            float2 f3 = __half22float2(*reinterpret_cast<__half2*>(&u.w));
            kv[0] = f0.x; kv[1] = f0.y; kv[2] = f1.x; kv[3] = f1.y;
            kv[4] = f2.x; kv[5] = f2.y; kv[6] = f3.x; kv[7] = f3.y;
        }
        float bv[8];
        {
            float4 b0 = __ldg(&bp[idx * 2]);
            float4 b1 = __ldg(&bp[idx * 2 + 1]);
            bv[0] = b0.x; bv[1] = b0.y; bv[2] = b0.z; bv[3] = b0.w;
            bv[4] = b1.x; bv[5] = b1.y; bv[6] = b1.z; bv[7] = b1.w;
        }
        float pv[24];
        {
            const float4* q4 = reinterpret_cast<const float4*>(p2b + (size_t)m8 * 3);
#pragma unroll
            for (int t = 0; t < 6; t++) {
                float4 qq = __ldg(&q4[t]);
                pv[4 * t + 0] = qq.x; pv[4 * t + 1] = qq.y;
                pv[4 * t + 2] = qq.z; pv[4 * t + 3] = qq.w;
            }
        }
#pragma unroll
        for (int e = 0; e < 8; e++) {
            float t = kv[e] * bv[e];
            a0 += t;
            ax = fmaf(t, pv[e * 3 + 0], ax);
            ay = fmaf(t, pv[e * 3 + 1], ay);
            az = fmaf(t, pv[e * 3 + 2], az);
        }
    }
    a0 = warp_sum(a0);
    ax = warp_sum(ax);
    ay = warp_sum(ay);
    az = warp_sum(az);
    if (lane == 0) {
        float av  = powf(PROB_S / (a0 + REG_S), POWER);
        float kb  = a0 * INV_SCALE;
        float w   = av * kb;
        float inv = 1.0f / (w + 1e-8f);
        g_w[gw] = w;
        g_corr[(size_t)gw * 3 + 0] = av * (ax * INV_SCALE) * inv;
        g_corr[(size_t)gw * 3 + 1] = av * (ay * INV_SCALE) * inv;
        g_corr[(size_t)gw * 3 + 2] = av * (az * INV_SCALE) * inv;
    }
}

// ---------------------------------------------------------------------------
// 8. Weighted Kabsch, one block per batch. 3x3 SVD via Jacobi (double) on t0.
// ---------------------------------------------------------------------------
__global__ void uot_kabsch_kernel(const float* __restrict__ p1, float* __restrict__ out) {
    int b    = blockIdx.x;
    int tid  = threadIdx.x;
    int lane = tid & 31;
    int wid  = tid >> 5;

    __shared__ float red[8][16];
    __shared__ float sh[16];

    float v[7];
#pragma unroll
    for (int j = 0; j < 7; j++) v[j] = 0.f;
    for (int n = tid; n < Nn; n += 256) {
        float wv = g_w[b * Nn + n];
        const float* q1 = p1 + ((size_t)b * Nn + n) * 3;
        const float* qc = g_corr + ((size_t)b * Nn + n) * 3;
        v[0] += wv;
        v[1] += wv * q1[0]; v[2] += wv * q1[1]; v[3] += wv * q1[2];
        v[4] += wv * qc[0]; v[5] += wv * qc[1]; v[6] += wv * qc[2];
    }
#pragma unroll
    for (int j = 0; j < 7; j++) {
        float t = warp_sum(v[j]);
        if (lane == 0) red[wid][j] = t;
    }
    __syncthreads();
    if (tid < 7) {
        float t = 0.f;
        for (int w8 = 0; w8 < 8; w8++) t += red[w8][tid];
        sh[tid] = t;
    }
    __syncthreads();
    float denom = sh[0] + 1e-5f;
    float ca0 = sh[1] / denom, ca1 = sh[2] / denom, ca2 = sh[3] / denom;
    float cb0 = sh[4] / denom, cb1 = sh[5] / denom, cb2 = sh[6] / denom;
    __syncthreads();

    float c9[9];
#pragma unroll
    for (int j = 0; j < 9; j++) c9[j] = 0.f;
    for (int n = tid; n < Nn; n += 256) {
        float wn = g_w[b * Nn + n] / denom;
        const float* q1 = p1 + ((size_t)b * Nn + n) * 3;
        const float* qc = g_corr + ((size_t)b * Nn + n) * 3;
        float a0 = q1[0] - ca0, a1 = q1[1] - ca1, a2 = q1[2] - ca2;
        float e0 = (qc[0] - cb0) * wn, e1 = (qc[1] - cb1) * wn, e2 = (qc[2] - cb2) * wn;
        c9[0] += a0 * e0; c9[1] += a0 * e1; c9[2] += a0 * e2;
        c9[3] += a1 * e0; c9[4] += a1 * e1; c9[5] += a1 * e2;
        c9[6] += a2 * e0; c9[7] += a2 * e1; c9[8] += a2 * e2;
    }
#pragma unroll
    for (int j = 0; j < 9; j++) {
        float t = warp_sum(c9[j]);
        if (lane == 0) red[wid][j] = t;
    }
    __syncthreads();
    if (tid < 9) {
        float t = 0.f;
        for (int w8 = 0; w8 < 8; w8++) t += red[w8][tid];
        sh[tid] = t;
    }
    __syncthreads();

    if (tid == 0) {
        double Cv[3][3];
        for (int r = 0; r < 3; r++)
            for (int c = 0; c < 3; c++) Cv[r][c] = (double)sh[r * 3 + c];

        double S[3][3];
        for (int i = 0; i < 3; i++)
            for (int j = 0; j < 3; j++)
                S[i][j] = Cv[0][i] * Cv[0][j] + Cv[1][i] * Cv[1][j] + Cv[2][i] * Cv[2][j];

        double V[3][3] = {{1, 0, 0}, {0, 1, 0}, {0, 0, 1}};
        const int PQ[3][2] = {{0, 1}, {0, 2}, {1, 2}};
        for (int sweep = 0; sweep < 45; sweep++) {
            int p = PQ[sweep % 3][0], q = PQ[sweep % 3][1];
            double apq = S[p][q];
            if (fabs(apq) < 1e-60) continue;
            double tau = (S[q][q] - S[p][p]) / (2.0 * apq);
            double t   = ((tau >= 0.0) ? 1.0 : -1.0) / (fabs(tau) + sqrt(1.0 + tau * tau));
            double cc  = 1.0 / sqrt(1.0 + t * t);
            double ss  = t * cc;
            for (int k = 0; k < 3; k++) {
                double skp = S[k][p], skq = S[k][q];
                S[k][p] = cc * skp - ss * skq;
                S[k][q] = ss * skp + cc * skq;
            }
            for (int k = 0; k < 3; k++) {
                double spk = S[p][k], sqk = S[q][k];
                S[p][k] = cc * spk - ss * sqk;
                S[q][k] = ss * spk + cc * sqk;
            }
            for (int k = 0; k < 3; k++) {
                double vkp = V[k][p], vkq = V[k][q];
                V[k][p] = cc * vkp - ss * vkq;
                V[k][q] = ss * vkp + cc * vkq;
            }
        }

        double lam[3] = {S[0][0], S[1][1], S[2][2]};
        int idx[3] = {0, 1, 2};
        for (int i = 0; i < 2; i++)
            for (int j = i + 1; j < 3; j++)
                if (lam[idx[j]] > lam[idx[i]]) { int t = idx[i]; idx[i] = idx[j]; idx[j] = t; }

        double Vs[3][3];
        for (int r = 0; r < 3; r++)
            for (int i = 0; i < 3; i++) Vs[r][i] = V[r][idx[i]];

        double U[3][3];
        for (int i = 0; i < 3; i++)
            for (int r = 0; r < 3; r++)
                U[r][i] = Cv[r][0] * Vs[0][i] + Cv[r][1] * Vs[1][i] + Cv[r][2] * Vs[2][i];

        {
            double nrm = sqrt(U[0][0]*U[0][0] + U[1][0]*U[1][0] + U[2][0]*U[2][0]);
            double inv = (nrm > 1e-150) ? 1.0 / nrm : 0.0;
            for (int r = 0; r < 3; r++) U[r][0] *= inv;
        }
        {
            double d01 = U[0][0]*U[0][1] + U[1][0]*U[1][1] + U[2][0]*U[2][1];
            for (int r = 0; r < 3; r++) U[r][1] -= d01 * U[r][0];
            double nrm = sqrt(U[0][1]*U[0][1] + U[1][1]*U[1][1] + U[2][1]*U[2][1]);
            double inv = (nrm > 1e-150) ? 1.0 / nrm : 0.0;
            for (int r = 0; r < 3; r++) U[r][1] *= inv;
        }
        {
            double d02 = U[0][0]*U[0][2] + U[1][0]*U[1][2] + U[2][0]*U[2][2];
            double d12 = U[0][1]*U[0][2] + U[1][1]*U[1][2] + U[2][1]*U[2][2];
            for (int r = 0; r < 3; r++) U[r][2] -= d02 * U[r][0] + d12 * U[r][1];
            double nrm = sqrt(U[0][2]*U[0][2] + U[1][2]*U[1][2] + U[2][2]*U[2][2]);
            if (nrm > 1e-12) {
                for (int r = 0; r < 3; r++) U[r][2] /= nrm;
            } else {
                U[0][2] = U[1][0]*U[2][1] - U[2][0]*U[1][1];
                U[1][2] = U[2][0]*U[0][1] - U[0][0]*U[2][1];
                U[2][2] = U[0][0]*U[1][1] - U[1][0]*U[0][1];
            }
        }

        double R[3][3];
        for (int r = 0; r < 3; r++)
            for (int c = 0; c < 3; c++)
                R[r][c] = Vs[r][0]*U[c][0] + Vs[r][1]*U[c][1] + Vs[r][2]*U[c][2];
        double det = R[0][0]*(R[1][1]*R[2][2] - R[1][2]*R[2][1])
                   - R[0][1]*(R[1][0]*R[2][2] - R[1][2]*R[2][0])
                   + R[0][2]*(R[1][0]*R[2][1] - R[1][1]*R[2][0]);
        if (!(det > 0.0)) {
            for (int r = 0; r < 3; r++)
                for (int c = 0; c < 3; c++)
                    R[r][c] -= 2.0 * Vs[r][2] * U[c][2];
        }

        double cad[3] = {ca0, ca1, ca2};
        double cbd[3] = {cb0, cb1, cb2};
        for (int r = 0; r < 3; r++) {
            double tr = cbd[r] - (R[r][0]*cad[0] + R[r][1]*cad[1] + R[r][2]*cad[2]);
            out[b * 12 + r * 4 + 0] = (float)R[r][0];
            out[b * 12 + r * 4 + 1] = (float)R[r][1];
            out[b * 12 + r * 4 + 2] = (float)R[r][2];
            out[b * 12 + r * 4 + 3] = (float)tr;
        }
    }
}

// ---------------------------------------------------------------------------
// Launch
// ---------------------------------------------------------------------------
extern "C" void kernel_launch(void* const* d_in, const int* in_sizes, int n_in,
                              void* d_out, int out_size) {
    const float* f1 = (const float*)d_in[0];
    const float* f2 = (const float*)d_in[1];
    const float* p1 = (const float*)d_in[2];
    const float* p2 = (const float*)d_in[3];
    float* out = (float*)d_out;

    static bool attr_set = false;
    if (!attr_set) {
        cudaFuncSetAttribute(uot_mma_exp_kernel,
                             cudaFuncAttributeMaxDynamicSharedMemorySize, SMEM_DYN);
        cudaFuncSetAttribute(uot_fused_kernel,
                             cudaFuncAttributeMaxDynamicSharedMemorySize, FUSED_SMEM);
        attr_set = true;
    }

    uot_norm_pack_kernel<<<8192, 256>>>(f1, f2);
    uot_mma_exp_kernel<<<dim3(32, 32, Bdim), 256, SMEM_DYN>>>();

    // iteration 1: colsum(a0=1/N) -> b1
    uot_colsum_init_kernel<<<dim3(8, 16, Bdim), 256>>>();
    uot_b_update_kernel<<<(Bdim * Mm + 255) / 256, 256>>>();

    // iterations 1..9: fused rowsum->a_t (smem tile), colsum(a_t) -> b_{t+1}
    for (int it = 0; it < 9; ++it) {
        uot_fused_kernel<<<dim3(512, Bdim), 256, FUSED_SMEM>>>();
        uot_b_update2_kernel<<<(Bdim * Mm + 255) / 256, 256>>>();
    }

    // iteration 10's rowsum: a_10, w, corr (uses b_10)
    uot_rowsum_final_kernel<<<4096, 256>>>(p2);

    uot_kabsch_kernel<<<Bdim, 256>>>(p1, out);
}

// round 15
// speedup vs baseline: 1.1678x; 1.0681x over previous
#include <cuda_runtime.h>
#include <cuda_fp16.h>
#include <cuda_bf16.h>
#include <math.h>
#include <cstdint>

// Problem constants
#define Bdim 8
#define Nn   4096
#define Mm   4096
#define Cc   256

#define INV_EPS 33.333333333333336f           // 1/0.03
#define POWER   0.94339622641509435f          // 0.5/(0.5+0.03)
#define PROB    0.000244140625f               // 1/4096

// K rescale: Ks = 2^41 * K  (exact power-of-two scaling)
#define LN_SCALE  28.41903440295776f          // 41*ln(2)
#define PROB_S    536870912.0f                // PROB * 2^41 = 2^29
#define REG_S     21990.23255552f             // 1e-8 * 2^41
#define INV_SCALE 4.547473508864641e-13f      // 2^-41

// Packed operand: [0:256)=hi, [256:512)=hi(f1)/lo(f2), [512:768)=lo(f1)/hi(f2)
#define KPACK 768

// ---------------------------------------------------------------------------
// Static device scratch (no dynamic allocation allowed)
// ---------------------------------------------------------------------------
__device__ __nv_bfloat16 g_f1p[(size_t)Bdim * Nn * KPACK];    // 50.3 MB
__device__ __nv_bfloat16 g_f2p[(size_t)Bdim * Mm * KPACK];    // 50.3 MB
__device__ __half g_K[(size_t)Bdim * Nn * Mm];                // 268 MB (scaled 2^41)
__device__ float g_b[Bdim * Mm];
__device__ float g_part[(size_t)Bdim * 32 * Mm];              // level-1 partials (4MB)
__device__ float g_part2[(size_t)Bdim * 512 * Mm];            // fused colsum partials (67MB)
__device__ float g_w[Bdim * Nn];
__device__ float g_corr[Bdim * Nn * 3];

__device__ __forceinline__ float warp_sum(float v) {
#pragma unroll
    for (int o = 16; o; o >>= 1) v += __shfl_xor_sync(0xffffffffu, v, o);
    return v;
}

__device__ __forceinline__ uint32_t smem_u32(const void* p) {
    uint32_t a;
    asm("{ .reg .u64 t; cvta.to.shared.u64 t, %1; cvt.u32.u64 %0, t; }"
        : "=r"(a) : "l"(p));
    return a;
}

// SW128 swizzle: byte_off = row*128 + seg*16  ->  row*128 + (seg*16 ^ ((row&7)*16))
#define SWZ128(x) ((x) ^ (((x) >> 3) & 0x70))

// ---------------------------------------------------------------------------
// mma.sync / ldmatrix / cp.async helpers (baseline PTX, NOT arch-gated)
// ---------------------------------------------------------------------------
__device__ __forceinline__ void ldsm_x4(uint32_t* r, uint32_t addr) {
    asm volatile("ldmatrix.sync.aligned.m8n8.x4.shared.b16 {%0,%1,%2,%3}, [%4];"
                 : "=r"(r[0]), "=r"(r[1]), "=r"(r[2]), "=r"(r[3]) : "r"(addr));
}
__device__ __forceinline__ void mma_bf16(float* d, const uint32_t* a,
                                         uint32_t b0, uint32_t b1) {
    asm volatile(
        "mma.sync.aligned.m16n8k16.row.col.f32.bf16.bf16.f32 "
        "{%0,%1,%2,%3}, {%4,%5,%6,%7}, {%8,%9}, {%0,%1,%2,%3};"
        : "+f"(d[0]), "+f"(d[1]), "+f"(d[2]), "+f"(d[3])
        : "r"(a[0]), "r"(a[1]), "r"(a[2]), "r"(a[3]), "r"(b0), "r"(b1));
}
__device__ __forceinline__ void cp_async16(uint32_t smem_dst, const void* gsrc) {
    asm volatile("cp.async.cg.shared.global [%0], [%1], 16;"
                 :: "r"(smem_dst), "l"(gsrc));
}
#define CP_COMMIT()  asm volatile("cp.async.commit_group;" ::: "memory")
#define CP_WAIT(N)   asm volatile("cp.async.wait_group %0;" :: "n"(N) : "memory")

// ---------------------------------------------------------------------------
// 1. L2-normalize + bf16 hi/lo split-pack (one warp per 256-float row)
//    f1 row: [hi | hi | lo];  f2 row: [hi | lo | hi]
//    Merged kernel: warps [0,32768) process f1, rest f2.
// ---------------------------------------------------------------------------
__device__ __forceinline__ void pack_store(__nv_bfloat16* dst, int e, float4 v, int which) {
    float vv[4] = {v.x, v.y, v.z, v.w};
    __nv_bfloat16 hi[4], lo[4];
#pragma unroll
    for (int i = 0; i < 4; i++) {
        hi[i] = __float2bfloat16(vv[i]);
        lo[i] = __float2bfloat16(vv[i] - __bfloat162float(hi[i]));
    }
    __nv_bfloat162 h01, h23, l01, l23;
    h01.x = hi[0]; h01.y = hi[1]; h23.x = hi[2]; h23.y = hi[3];
    l01.x = lo[0]; l01.y = lo[1]; l23.x = lo[2]; l23.y = lo[3];
    *reinterpret_cast<__nv_bfloat162*>(dst + e)     = h01;
    *reinterpret_cast<__nv_bfloat162*>(dst + e + 2) = h23;
    if (which == 0) {
        *reinterpret_cast<__nv_bfloat162*>(dst + 256 + e)     = h01;
        *reinterpret_cast<__nv_bfloat162*>(dst + 256 + e + 2) = h23;
        *reinterpret_cast<__nv_bfloat162*>(dst + 512 + e)     = l01;
        *reinterpret_cast<__nv_bfloat162*>(dst + 512 + e + 2) = l23;
    } else {
        *reinterpret_cast<__nv_bfloat162*>(dst + 256 + e)     = l01;
        *reinterpret_cast<__nv_bfloat162*>(dst + 256 + e + 2) = l23;
        *reinterpret_cast<__nv_bfloat162*>(dst + 512 + e)     = h01;
        *reinterpret_cast<__nv_bfloat162*>(dst + 512 + e + 2) = h23;
    }
}

__global__ void uot_norm_pack_kernel(const float* __restrict__ f1,
                                     const float* __restrict__ f2) {
    int gwa  = (blockIdx.x * blockDim.x + threadIdx.x) >> 5;   // 0..65535
    int lane = threadIdx.x & 31;
    int which = (gwa >= Bdim * Nn) ? 1 : 0;
    int gw = which ? (gwa - Bdim * Nn) : gwa;
    const float* src = which ? f2 : f1;

    const float4* s4 = reinterpret_cast<const float4*>(src) + (size_t)gw * 64;
    float4 v0 = s4[lane];
    float4 v1 = s4[lane + 32];
    float ss = v0.x*v0.x + v0.y*v0.y + v0.z*v0.z + v0.w*v0.w
             + v1.x*v1.x + v1.y*v1.y + v1.z*v1.z + v1.w*v1.w;
    ss = warp_sum(ss);
    float inv = 1.0f / sqrtf(ss + 1e-8f);
    v0.x *= inv; v0.y *= inv; v0.z *= inv; v0.w *= inv;
    v1.x *= inv; v1.y *= inv; v1.z *= inv; v1.w *= inv;

    __nv_bfloat16* dst = (which ? g_f2p : g_f1p) + (size_t)gw * KPACK;
    int e = lane * 4;
    pack_store(dst, e, v0, which);
    pack_store(dst, e + 128, v1, which);
}

// ---------------------------------------------------------------------------
// 2. HMMA GEMM: Ks = 2^41*exp((f1.f2-1)/eps), fp16 store,
//    PLUS fused init colsum: per-tile 128-row column sums -> g_part[b][ry][c].
// ---------------------------------------------------------------------------
#define STAGE_BYTES 16384                 // 128 rows x 128 B
#define BUF_BYTES   32768                 // A + B per stage
#define SMEM_DYN    98304                 // 3 bufs

__global__ __launch_bounds__(256) void uot_mma_exp_kernel() {
    extern __shared__ char smem[];
    uint32_t sb = smem_u32(smem);
    int tid  = threadIdx.x;
    int wid  = tid >> 5;
    int lane = tid & 31;

    int bz = blockIdx.z;
    int r0 = blockIdx.y * 128;     // output rows  (f1 index)
    int c0 = blockIdx.x * 128;     // output cols  (f2 index)

    const char* Abase = reinterpret_cast<const char*>(
        g_f1p + ((size_t)bz * Nn + r0) * KPACK);
    const char* Bbase = reinterpret_cast<const char*>(
        g_f2p + ((size_t)bz * Mm + c0) * KPACK);

    int segid[8];
#pragma unroll
    for (int i = 0; i < 8; i++) segid[i] = tid + i * 256;

    auto prefetch = [&](int st) {
        uint32_t base = sb + (uint32_t)(st % 3) * BUF_BYTES;
        const char* Asrc = Abase + st * 128;
        const char* Bsrc = Bbase + st * 128;
#pragma unroll
        for (int i = 0; i < 8; i++) {
            int l   = segid[i];
            int isB = l >> 10;
            int row = (l >> 3) & 127;
            int seg = l & 7;
            const char* src = (isB ? Bsrc : Asrc) + (size_t)row * (KPACK * 2) + seg * 16;
            uint32_t dst = base + isB * STAGE_BYTES + SWZ128(row * 128 + seg * 16);
            cp_async16(dst, src);
        }
    };

    int mt = (wid & 3) * 32;        // warp row offset (A side)
    int ntw = (wid >> 2) * 64;      // warp col offset (B side)

    int arow0 = mt + (lane & 15);
    int aks   = lane >> 4;
    uint32_t aoff0 = arow0 * 128;
    uint32_t axor0 = (uint32_t)((arow0 & 7) * 16);
    int arow1 = arow0 + 16;
    uint32_t aoff1 = arow1 * 128;
    uint32_t axor1 = (uint32_t)((arow1 & 7) * 16);

    int brow = ntw + ((lane & 7) | ((lane >> 1) & 8));
    int bks  = (lane >> 3) & 1;
    uint32_t boff = brow * 128;
    uint32_t bxor = (uint32_t)((brow & 7) * 16);

    float acc[2][8][4];
#pragma unroll
    for (int i = 0; i < 2; i++)
#pragma unroll
        for (int j = 0; j < 8; j++)
#pragma unroll
            for (int k = 0; k < 4; k++) acc[i][j][k] = 0.0f;

    prefetch(0); CP_COMMIT();
    prefetch(1); CP_COMMIT();

    for (int st = 0; st < 12; st++) {
        CP_WAIT(1);
        __syncthreads();
        if (st + 2 < 12) { prefetch(st + 2); CP_COMMIT(); }

        uint32_t baseA = sb + (uint32_t)(st % 3) * BUF_BYTES;
        uint32_t baseB = baseA + STAGE_BYTES;
#pragma unroll
        for (int kc = 0; kc < 4; kc++) {
            uint32_t kseg = (uint32_t)((kc * 2 + aks) * 16);
            uint32_t a0[4], a1[4];
            ldsm_x4(a0, baseA + aoff0 + (kseg ^ axor0));
            ldsm_x4(a1, baseA + aoff1 + (kseg ^ axor1));
            uint32_t kbseg = (uint32_t)((kc * 2 + bks) * 16);
#pragma unroll
            for (int nb = 0; nb < 4; nb++) {
                uint32_t bfrag[4];
                ldsm_x4(bfrag, baseB + boff + (uint32_t)(nb * 16 * 128) + (kbseg ^ bxor));
                mma_bf16(acc[0][2 * nb + 0], a0, bfrag[0], bfrag[1]);
                mma_bf16(acc[0][2 * nb + 1], a0, bfrag[2], bfrag[3]);
                mma_bf16(acc[1][2 * nb + 0], a1, bfrag[0], bfrag[1]);
                mma_bf16(acc[1][2 * nb + 1], a1, bfrag[2], bfrag[3]);
            }
        }
    }
    __syncthreads();   // all ldsm reads done before smem reuse below

    // --- Epilogue: exp -> fp16 store + per-tile column sums ---
    int g  = lane >> 2;
    int tg = lane & 3;
    __half* Kout = g_K + ((size_t)bz * Nn + r0) * Mm + c0;
    float cs[8][2];
#pragma unroll
    for (int ni = 0; ni < 8; ni++) { cs[ni][0] = 0.f; cs[ni][1] = 0.f; }
#pragma unroll
    for (int mi = 0; mi < 2; mi++) {
        int rowA = mt + mi * 16 + g;
#pragma unroll
        for (int ni = 0; ni < 8; ni++) {
            int col = ntw + ni * 8 + tg * 2;
            float* d = acc[mi][ni];
            float e0 = fminf(__expf(fmaf(d[0] - 1.0f, INV_EPS, LN_SCALE)), 60000.0f);
            float e1 = fminf(__expf(fmaf(d[1] - 1.0f, INV_EPS, LN_SCALE)), 60000.0f);
            float e2 = fminf(__expf(fmaf(d[2] - 1.0f, INV_EPS, LN_SCALE)), 60000.0f);
            float e3 = fminf(__expf(fmaf(d[3] - 1.0f, INV_EPS, LN_SCALE)), 60000.0f);
            *reinterpret_cast<__half2*>(&Kout[(size_t)rowA * Mm + col]) =
                __floats2half2_rn(e0, e1);
            *reinterpret_cast<__half2*>(&Kout[(size_t)(rowA + 8) * Mm + col]) =
                __floats2half2_rn(e2, e3);
            cs[ni][0] += e0 + e2;
            cs[ni][1] += e1 + e3;
        }
    }
    // reduce over the 8 g-lanes (same tg): shfl_xor 4/8/16 flips g bits
    float* csm = reinterpret_cast<float*>(smem);   // 8 warps x 64 cols
#pragma unroll
    for (int ni = 0; ni < 8; ni++) {
#pragma unroll
        for (int k = 0; k < 2; k++) {
            float v = cs[ni][k];
            v += __shfl_xor_sync(0xffffffffu, v, 4);
            v += __shfl_xor_sync(0xffffffffu, v, 8);
            v += __shfl_xor_sync(0xffffffffu, v, 16);
            if (g == 0) csm[wid * 64 + ni * 8 + tg * 2 + k] = v;
        }
    }
    __syncthreads();
    if (tid < 128) {
        int c = tid;
        float s = (c < 64)
            ? csm[0 * 64 + c] + csm[1 * 64 + c] + csm[2 * 64 + c] + csm[3 * 64 + c]
            : csm[4 * 64 + (c - 64)] + csm[5 * 64 + (c - 64)]
            + csm[6 * 64 + (c - 64)] + csm[7 * 64 + (c - 64)];
        g_part[((size_t)(bz * 32) + blockIdx.y) * Mm + c0 + c] = s;
    }
}

// ---------------------------------------------------------------------------
// 3. b = (prob2*S / (scale * sum of cnt partials + 1e-8*S)) ^ power
// ---------------------------------------------------------------------------
__global__ void uot_b_update_kernel(int cnt, float scale) {
    int i = blockIdx.x * blockDim.x + threadIdx.x;
    if (i >= Bdim * Mm) return;
    int b = i >> 12;
    int m = i & 4095;
    const float* p = g_part + (size_t)(b * 32) * Mm + m;
    float s = 0.f;
    for (int j = 0; j < cnt; j++) s += p[(size_t)j * Mm];
    g_b[i] = powf(PROB_S / (s * scale + REG_S), POWER);
}

// ---------------------------------------------------------------------------
// 4. Fused Sinkhorn pass (4096 blocks — wave-safe): single DRAM read.
//    Block = 8 rows x 4096 cols. Phase a: warp-per-row rowsum + stage row to
//    smem. Phase b: colsum partials from smem (conflict-free).
// ---------------------------------------------------------------------------
#define FUSED_ROWS 8
#define FUSED_SMEM (FUSED_ROWS * Mm * 2 + 64)     // 65600

__global__ __launch_bounds__(256) void uot_fused_kernel() {
    extern __shared__ char fsm[];
    __half* tile = reinterpret_cast<__half*>(fsm);                 // 8 x 4096 halves
    float*  sh_a = reinterpret_cast<float*>(fsm + FUSED_ROWS * Mm * 2);
    int tid  = threadIdx.x;
    int wid  = tid >> 5;
    int lane = tid & 31;
    int rb = blockIdx.x;               // 0..511
    int b  = blockIdx.y;               // 0..7
    int row0 = rb * FUSED_ROWS;
    const __half* Kbase = g_K + ((size_t)b * Nn + row0) * Mm;
    const float4* bp = reinterpret_cast<const float4*>(g_b + b * Mm);

    // phase a: warp wid handles row wid (stream from DRAM, dot + stage)
    {
        const uint4* Kp = reinterpret_cast<const uint4*>(Kbase + (size_t)wid * Mm);
        uint4* Tp = reinterpret_cast<uint4*>(tile + (size_t)wid * Mm);
        float acc = 0.f;
#pragma unroll 4
        for (int it = 0; it < 16; it++) {
            int idx = it * 32 + lane;
            uint4 u = Kp[idx];
            Tp[idx] = u;
            float2 f0 = __half22float2(*reinterpret_cast<__half2*>(&u.x));
            float2 f1 = __half22float2(*reinterpret_cast<__half2*>(&u.y));
            float2 f2 = __half22float2(*reinterpret_cast<__half2*>(&u.z));
            float2 f3 = __half22float2(*reinterpret_cast<__half2*>(&u.w));
            float4 b0 = __ldg(&bp[idx * 2]);
            float4 b1 = __ldg(&bp[idx * 2 + 1]);
            acc += f0.x * b0.x + f0.y * b0.y + f1.x * b0.z + f1.y * b0.w
                 + f2.x * b1.x + f2.y * b1.y + f3.x * b1.z + f3.y * b1.w;
        }
        acc = warp_sum(acc);
        if (lane == 0) sh_a[wid] = powf(PROB_S / (acc + REG_S), POWER);
    }
    __syncthreads();

    float av[FUSED_ROWS];
#pragma unroll
    for (int r = 0; r < FUSED_ROWS; r++) av[r] = sh_a[r];

    // phase b: thread owns 16B segments tid and tid+256 (cols seg*8..+7)
    float ca[16];
#pragma unroll
    for (int j = 0; j < 16; j++) ca[j] = 0.f;
#pragma unroll
    for (int r = 0; r < FUSED_ROWS; r++) {
        const uint4* Tp = reinterpret_cast<const uint4*>(tile + (size_t)r * Mm);
        uint4 u0 = Tp[tid];
        uint4 u1 = Tp[tid + 256];
        float a = av[r];
        float2 f;
        f = __half22float2(*reinterpret_cast<__half2*>(&u0.x)); ca[0]  = fmaf(a, f.x, ca[0]);  ca[1]  = fmaf(a, f.y, ca[1]);
        f = __half22float2(*reinterpret_cast<__half2*>(&u0.y)); ca[2]  = fmaf(a, f.x, ca[2]);  ca[3]  = fmaf(a, f.y, ca[3]);
        f = __half22float2(*reinterpret_cast<__half2*>(&u0.z)); ca[4]  = fmaf(a, f.x, ca[4]);  ca[5]  = fmaf(a, f.y, ca[5]);
        f = __half22float2(*reinterpret_cast<__half2*>(&u0.w)); ca[6]  = fmaf(a, f.x, ca[6]);  ca[7]  = fmaf(a, f.y, ca[7]);
        f = __half22float2(*reinterpret_cast<__half2*>(&u1.x)); ca[8]  = fmaf(a, f.x, ca[8]);  ca[9]  = fmaf(a, f.y, ca[9]);
        f = __half22float2(*reinterpret_cast<__half2*>(&u1.y)); ca[10] = fmaf(a, f.x, ca[10]); ca[11] = fmaf(a, f.y, ca[11]);
        f = __half22float2(*reinterpret_cast<__half2*>(&u1.z)); ca[12] = fmaf(a, f.x, ca[12]); ca[13] = fmaf(a, f.y, ca[13]);
        f = __half22float2(*reinterpret_cast<__half2*>(&u1.w)); ca[14] = fmaf(a, f.x, ca[14]); ca[15] = fmaf(a, f.y, ca[15]);
    }
    float* prow = g_part2 + ((size_t)(b * 512 + rb)) * Mm;
    float4* d0 = reinterpret_cast<float4*>(prow + tid * 8);
    d0[0] = make_float4(ca[0], ca[1], ca[2],  ca[3]);
    d0[1] = make_float4(ca[4], ca[5], ca[6],  ca[7]);
    float4* d1 = reinterpret_cast<float4*>(prow + (tid + 256) * 8);
    d1[0] = make_float4(ca[8],  ca[9],  ca[10], ca[11]);
    d1[1] = make_float4(ca[12], ca[13], ca[14], ca[15]);
}

// ---------------------------------------------------------------------------
// 5. Reduce 512 fused partials -> 8 level-1 partials (1024 blocks, full BW)
// ---------------------------------------------------------------------------
__global__ void uot_reduce_kernel() {
    int m = blockIdx.x * 256 + threadIdx.x;   // 0..4095
    int j = blockIdx.y;                        // 0..7
    int b = blockIdx.z;
    const float* p = g_part2 + ((size_t)(b * 512 + j * 64)) * Mm + m;
    float s0 = 0.f, s1 = 0.f, s2 = 0.f, s3 = 0.f;
#pragma unroll 4
    for (int t = 0; t < 64; t += 4) {
        s0 += p[(size_t)(t + 0) * Mm];
        s1 += p[(size_t)(t + 1) * Mm];
        s2 += p[(size_t)(t + 2) * Mm];
        s3 += p[(size_t)(t + 3) * Mm];
    }
    g_part[(size_t)(b * 32 + j) * Mm + m] = (s0 + s1) + (s2 + s3);
}

// ---------------------------------------------------------------------------
// 6. Final fused pass: Ks·b and Ks·(b*p2_{xyz}) -> a, w, corr
// ---------------------------------------------------------------------------
__global__ void uot_rowsum_final_kernel(const float* __restrict__ p2) {
    int gw   = (blockIdx.x * blockDim.x + threadIdx.x) >> 5;
    int lane = threadIdx.x & 31;
    if (gw >= Bdim * Nn) return;
    int b = gw >> 12;
    int n = gw & 4095;
    const uint4*  Kp  = reinterpret_cast<const uint4*>(g_K + ((size_t)b * Nn + n) * Mm);
    const float4* bp  = reinterpret_cast<const float4*>(g_b + b * Mm);
    const float*  p2b = p2 + (size_t)b * Mm * 3;

    float a0 = 0.f, ax = 0.f, ay = 0.f, az = 0.f;
    for (int it = 0; it < 16; it++) {
        int idx = it * 32 + lane;
        int m8  = idx * 8;
        uint4 u = Kp[idx];
        float kv[8];
        {
            float2 f0 = __half22float2(*reinterpret_cast<__half2*>(&u.x));
            float2 f1 = __half22float2(*reinterpret_cast<__half2*>(&u.y));
            float2 f2 = __half22float2(*reinterpret_cast<__half2*>(&u.z));
            float2 f3 = __half22float2(*reinterpret_cast<__half2*>(&u.w));
            kv[0] = f0.x; kv[1] = f0.y; kv[2] = f1.x; kv[3] = f1.y;
            kv[4] = f2.x; kv[5] = f2.y; kv[6] = f3.x; kv[7] = f3.y;
        }
        float bv[8];
        {
            float4 b0 = __ldg(&bp[idx * 2]);
            float4 b1 = __ldg(&bp[idx * 2 + 1]);
            bv[0] = b0.x; bv[1] = b0.y; bv[2] = b0.z; bv[3] = b0.w;
            bv[4] = b1.x; bv[5] = b1.y; bv[6] = b1.z; bv[7] = b1.w;
        }
        float pv[24];
        {
            const float4* q4 = reinterpret_cast<const float4*>(p2b + (size_t)m8 * 3);
#pragma unroll
            for (int t = 0; t < 6; t++) {
                float4 qq = __ldg(&q4[t]);
                pv[4 * t + 0] = qq.x; pv[4 * t + 1] = qq.y;
                pv[4 * t + 2] = qq.z; pv[4 * t + 3] = qq.w;
            }
        }
#pragma unroll
        for (int e = 0; e < 8; e++) {
            float t = kv[e] * bv[e];
            a0 += t;
            ax = fmaf(t, pv[e * 3 + 0], ax);
            ay = fmaf(t, pv[e * 3 + 1], ay);
            az = fmaf(t, pv[e * 3 + 2], az);
        }
    }
    a0 = warp_sum(a0);
    ax = warp_sum(ax);
    ay = warp_sum(ay);
    az = warp_sum(az);
    if (lane == 0) {
        float av  = powf(PROB_S / (a0 + REG_S), POWER);
        float kb  = a0 * INV_SCALE;
        float w   = av * kb;
        float inv = 1.0f / (w + 1e-8f);
        g_w[gw] = w;
        g_corr[(size_t)gw * 3 + 0] = av * (ax * INV_SCALE) * inv;
        g_corr[(size_t)gw * 3 + 1] = av * (ay * INV_SCALE) * inv;
        g_corr[(size_t)gw * 3 + 2] = av * (az * INV_SCALE) * inv;
    }
}

// ---------------------------------------------------------------------------
// 7. Weighted Kabsch, one block per batch. 3x3 SVD via Jacobi (double) on t0.
// ---------------------------------------------------------------------------
__global__ void uot_kabsch_kernel(const float* __restrict__ p1, float* __restrict__ out) {
    int b    = blockIdx.x;
    int tid  = threadIdx.x;
    int lane = tid & 31;
    int wid  = tid >> 5;

    __shared__ float red[8][16];
    __shared__ float sh[16];

    float v[7];
#pragma unroll
    for (int j = 0; j < 7; j++) v[j] = 0.f;
    for (int n = tid; n < Nn; n += 256) {
        float wv = g_w[b * Nn + n];
        const float* q1 = p1 + ((size_t)b * Nn + n) * 3;
        const float* qc = g_corr + ((size_t)b * Nn + n) * 3;
        v[0] += wv;
        v[1] += wv * q1[0]; v[2] += wv * q1[1]; v[3] += wv * q1[2];
        v[4] += wv * qc[0]; v[5] += wv * qc[1]; v[6] += wv * qc[2];
    }
#pragma unroll
    for (int j = 0; j < 7; j++) {
        float t = warp_sum(v[j]);
        if (lane == 0) red[wid][j] = t;
    }
    __syncthreads();
    if (tid < 7) {
        float t = 0.f;
        for (int w8 = 0; w8 < 8; w8++) t += red[w8][tid];
        sh[tid] = t;
    }
    __syncthreads();
    float denom = sh[0] + 1e-5f;
    float ca0 = sh[1] / denom, ca1 = sh[2] / denom, ca2 = sh[3] / denom;
    float cb0 = sh[4] / denom, cb1 = sh[5] / denom, cb2 = sh[6] / denom;
    __syncthreads();

    float c9[9];
#pragma unroll
    for (int j = 0; j < 9; j++) c9[j] = 0.f;
    for (int n = tid; n < Nn; n += 256) {
        float wn = g_w[b * Nn + n] / denom;
        const float* q1 = p1 + ((size_t)b * Nn + n) * 3;
        const float* qc = g_corr + ((size_t)b * Nn + n) * 3;
        float a0 = q1[0] - ca0, a1 = q1[1] - ca1, a2 = q1[2] - ca2;
        float e0 = (qc[0] - cb0) * wn, e1 = (qc[1] - cb1) * wn, e2 = (qc[2] - cb2) * wn;
        c9[0] += a0 * e0; c9[1] += a0 * e1; c9[2] += a0 * e2;
        c9[3] += a1 * e0; c9[4] += a1 * e1; c9[5] += a1 * e2;
        c9[6] += a2 * e0; c9[7] += a2 * e1; c9[8] += a2 * e2;
    }
#pragma unroll
    for (int j = 0; j < 9; j++) {
        float t = warp_sum(c9[j]);
        if (lane == 0) red[wid][j] = t;
    }
    __syncthreads();
    if (tid < 9) {
        float t = 0.f;
        for (int w8 = 0; w8 < 8; w8++) t += red[w8][tid];
        sh[tid] = t;
    }
    __syncthreads();

    if (tid == 0) {
        double Cv[3][3];
        for (int r = 0; r < 3; r++)
            for (int c = 0; c < 3; c++) Cv[r][c] = (double)sh[r * 3 + c];

        double S[3][3];
        for (int i = 0; i < 3; i++)
            for (int j = 0; j < 3; j++)
                S[i][j] = Cv[0][i] * Cv[0][j] + Cv[1][i] * Cv[1][j] + Cv[2][i] * Cv[2][j];

        double V[3][3] = {{1, 0, 0}, {0, 1, 0}, {0, 0, 1}};
        const int PQ[3][2] = {{0, 1}, {0, 2}, {1, 2}};
        for (int sweep = 0; sweep < 45; sweep++) {
            int p = PQ[sweep % 3][0], q = PQ[sweep % 3][1];
            double apq = S[p][q];
            if (fabs(apq) < 1e-60) continue;
            double tau = (S[q][q] - S[p][p]) / (2.0 * apq);
            double t   = ((tau >= 0.0) ? 1.0 : -1.0) / (fabs(tau) + sqrt(1.0 + tau * tau));
            double cc  = 1.0 / sqrt(1.0 + t * t);
            double ss  = t * cc;
            for (int k = 0; k < 3; k++) {
                double skp = S[k][p], skq = S[k][q];
                S[k][p] = cc * skp - ss * skq;
                S[k][q] = ss * skp + cc * skq;
            }
            for (int k = 0; k < 3; k++) {
                double spk = S[p][k], sqk = S[q][k];
                S[p][k] = cc * spk - ss * sqk;
                S[q][k] = ss * spk + cc * sqk;
            }
            for (int k = 0; k < 3; k++) {
                double vkp = V[k][p], vkq = V[k][q];
                V[k][p] = cc * vkp - ss * vkq;
                V[k][q] = ss * vkp + cc * vkq;
            }
        }

        double lam[3] = {S[0][0], S[1][1], S[2][2]};
        int idx[3] = {0, 1, 2};
        for (int i = 0; i < 2; i++)
            for (int j = i + 1; j < 3; j++)
                if (lam[idx[j]] > lam[idx[i]]) { int t = idx[i]; idx[i] = idx[j]; idx[j] = t; }

        double Vs[3][3];
        for (int r = 0; r < 3; r++)
            for (int i = 0; i < 3; i++) Vs[r][i] = V[r][idx[i]];

        double U[3][3];
        for (int i = 0; i < 3; i++)
            for (int r = 0; r < 3; r++)
                U[r][i] = Cv[r][0] * Vs[0][i] + Cv[r][1] * Vs[1][i] + Cv[r][2] * Vs[2][i];

        {
            double nrm = sqrt(U[0][0]*U[0][0] + U[1][0]*U[1][0] + U[2][0]*U[2][0]);
            double inv = (nrm > 1e-150) ? 1.0 / nrm : 0.0;
            for (int r = 0; r < 3; r++) U[r][0] *= inv;
        }
        {
            double d01 = U[0][0]*U[0][1] + U[1][0]*U[1][1] + U[2][0]*U[2][1];
            for (int r = 0; r < 3; r++) U[r][1] -= d01 * U[r][0];
            double nrm = sqrt(U[0][1]*U[0][1] + U[1][1]*U[1][1] + U[2][1]*U[2][1]);
            double inv = (nrm > 1e-150) ? 1.0 / nrm : 0.0;
            for (int r = 0; r < 3; r++) U[r][1] *= inv;
        }
        {
            double d02 = U[0][0]*U[0][2] + U[1][0]*U[1][2] + U[2][0]*U[2][2];
            double d12 = U[0][1]*U[0][2] + U[1][1]*U[1][2] + U[2][1]*U[2][2];
            for (int r = 0; r < 3; r++) U[r][2] -= d02 * U[r][0] + d12 * U[r][1];
            double nrm = sqrt(U[0][2]*U[0][2] + U[1][2]*U[1][2] + U[2][2]*U[2][2]);
            if (nrm > 1e-12) {
                for (int r = 0; r < 3; r++) U[r][2] /= nrm;
            } else {
                U[0][2] = U[1][0]*U[2][1] - U[2][0]*U[1][1];
                U[1][2] = U[2][0]*U[0][1] - U[0][0]*U[2][1];
                U[2][2] = U[0][0]*U[1][1] - U[1][0]*U[0][1];
            }
        }

        double R[3][3];
        for (int r = 0; r < 3; r++)
            for (int c = 0; c < 3; c++)
                R[r][c] = Vs[r][0]*U[c][0] + Vs[r][1]*U[c][1] + Vs[r][2]*U[c][2];
        double det = R[0][0]*(R[1][1]*R[2][2] - R[1][2]*R[2][1])
                   - R[0][1]*(R[1][0]*R[2][2] - R[1][2]*R[2][0])
                   + R[0][2]*(R[1][0]*R[2][1] - R[1][1]*R[2][0]);
        if (!(det > 0.0)) {
            for (int r = 0; r < 3; r++)
                for (int c = 0; c < 3; c++)
                    R[r][c] -= 2.0 * Vs[r][2] * U[c][2];
        }

        double cad[3] = {ca0, ca1, ca2};
        double cbd[3] = {cb0, cb1, cb2};
        for (int r = 0; r < 3; r++) {
            double tr = cbd[r] - (R[r][0]*cad[0] + R[r][1]*cad[1] + R[r][2]*cad[2]);
            out[b * 12 + r * 4 + 0] = (float)R[r][0];
            out[b * 12 + r * 4 + 1] = (float)R[r][1];
            out[b * 12 + r * 4 + 2] = (float)R[r][2];
            out[b * 12 + r * 4 + 3] = (float)tr;
        }
    }
}

// ---------------------------------------------------------------------------
// Launch
// ---------------------------------------------------------------------------
extern "C" void kernel_launch(void* const* d_in, const int* in_sizes, int n_in,
                              void* d_out, int out_size) {
    const float* f1 = (const float*)d_in[0];
    const float* f2 = (const float*)d_in[1];
    const float* p1 = (const float*)d_in[2];
    const float* p2 = (const float*)d_in[3];
    float* out = (float*)d_out;

    static bool attr_set = false;
    if (!attr_set) {
        cudaFuncSetAttribute(uot_mma_exp_kernel,
                             cudaFuncAttributeMaxDynamicSharedMemorySize, SMEM_DYN);
        cudaFuncSetAttribute(uot_fused_kernel,
                             cudaFuncAttributeMaxDynamicSharedMemorySize, FUSED_SMEM);
        attr_set = true;
    }

    uot_norm_pack_kernel<<<8192, 256>>>(f1, f2);
    // GEMM also produces init colsum partials (32 per batch) in g_part
    uot_mma_exp_kernel<<<dim3(32, 32, Bdim), 256, SMEM_DYN>>>();

    // iteration 1: b1 from GEMM-fused colsum (32 partials, scaled by a0=1/N)
    uot_b_update_kernel<<<(Bdim * Mm + 255) / 256, 256>>>(32, PROB);

    // iterations 1..9: fused rowsum->a_t (smem tile), colsum(a_t) -> b_{t+1}
    for (int it = 0; it < 9; ++it) {
        uot_fused_kernel<<<dim3(512, Bdim), 256, FUSED_SMEM>>>();
        uot_reduce_kernel<<<dim3(16, 8, Bdim), 256>>>();
        uot_b_update_kernel<<<(Bdim * Mm + 255) / 256, 256>>>(8, 1.0f);
    }

    // iteration 10's rowsum: a_10, w, corr (uses b_10)
    uot_rowsum_final_kernel<<<4096, 256>>>(p2);

    uot_kabsch_kernel<<<Bdim, 256>>>(p1, out);
}

// round 16
// speedup vs baseline: 1.1899x; 1.0189x over previous
#include <cuda_runtime.h>
#include <cuda_fp16.h>
#include <cuda_bf16.h>
#include <math.h>
#include <cstdint>

// Problem constants
#define Bdim 8
#define Nn   4096
#define Mm   4096
#define Cc   256

#define INV_EPS 33.333333333333336f           // 1/0.03
#define POWER   0.94339622641509435f          // 0.5/(0.5+0.03)
#define PROB    0.000244140625f               // 1/4096

// K rescale: Ks = 2^41 * K  (exact power-of-two scaling)
#define LN_SCALE  28.41903440295776f          // 41*ln(2)
#define PROB_S    536870912.0f                // PROB * 2^41 = 2^29
#define REG_S     21990.23255552f             // 1e-8 * 2^41
#define INV_SCALE 4.547473508864641e-13f      // 2^-41

// Packed operand: [0:256)=hi, [256:512)=hi(f1)/lo(f2), [512:768)=lo(f1)/hi(f2)
#define KPACK 768

// ---------------------------------------------------------------------------
// Static device scratch (no dynamic allocation allowed)
// ---------------------------------------------------------------------------
__device__ __nv_bfloat16 g_f1p[(size_t)Bdim * Nn * KPACK];    // 50.3 MB
__device__ __nv_bfloat16 g_f2p[(size_t)Bdim * Mm * KPACK];    // 50.3 MB
__device__ __half g_K[(size_t)Bdim * Nn * Mm];                // 268 MB (scaled 2^41)
__device__ float g_b[Bdim * Mm];
__device__ float g_part[(size_t)Bdim * 32 * Mm];              // level-1 partials (4MB)
__device__ float g_part2[(size_t)Bdim * 512 * Mm];            // fused colsum partials (67MB)
__device__ float g_w[Bdim * Nn];
__device__ float g_corr[Bdim * Nn * 3];

__device__ __forceinline__ float warp_sum(float v) {
#pragma unroll
    for (int o = 16; o; o >>= 1) v += __shfl_xor_sync(0xffffffffu, v, o);
    return v;
}

__device__ __forceinline__ uint32_t smem_u32(const void* p) {
    uint32_t a;
    asm("{ .reg .u64 t; cvta.to.shared.u64 t, %1; cvt.u32.u64 %0, t; }"
        : "=r"(a) : "l"(p));
    return a;
}

// SW128 swizzle: byte_off = row*128 + seg*16  ->  row*128 + (seg*16 ^ ((row&7)*16))
#define SWZ128(x) ((x) ^ (((x) >> 3) & 0x70))

// ---------------------------------------------------------------------------
// mma.sync / ldmatrix / cp.async helpers (baseline PTX, NOT arch-gated)
// ---------------------------------------------------------------------------
__device__ __forceinline__ void ldsm_x4(uint32_t* r, uint32_t addr) {
    asm volatile("ldmatrix.sync.aligned.m8n8.x4.shared.b16 {%0,%1,%2,%3}, [%4];"
                 : "=r"(r[0]), "=r"(r[1]), "=r"(r[2]), "=r"(r[3]) : "r"(addr));
}
__device__ __forceinline__ void mma_bf16(float* d, const uint32_t* a,
                                         uint32_t b0, uint32_t b1) {
    asm volatile(
        "mma.sync.aligned.m16n8k16.row.col.f32.bf16.bf16.f32 "
        "{%0,%1,%2,%3}, {%4,%5,%6,%7}, {%8,%9}, {%0,%1,%2,%3};"
        : "+f"(d[0]), "+f"(d[1]), "+f"(d[2]), "+f"(d[3])
        : "r"(a[0]), "r"(a[1]), "r"(a[2]), "r"(a[3]), "r"(b0), "r"(b1));
}
__device__ __forceinline__ void cp_async16(uint32_t smem_dst, const void* gsrc) {
    asm volatile("cp.async.cg.shared.global [%0], [%1], 16;"
                 :: "r"(smem_dst), "l"(gsrc));
}
#define CP_COMMIT()  asm volatile("cp.async.commit_group;" ::: "memory")
#define CP_WAIT(N)   asm volatile("cp.async.wait_group %0;" :: "n"(N) : "memory")

// ---------------------------------------------------------------------------
// 1. L2-normalize + bf16 hi/lo split-pack (one warp per 256-float row)
//    f1 row: [hi | hi | lo];  f2 row: [hi | lo | hi]
//    Merged kernel: warps [0,32768) process f1, rest f2.
// ---------------------------------------------------------------------------
__device__ __forceinline__ void pack_store(__nv_bfloat16* dst, int e, float4 v, int which) {
    float vv[4] = {v.x, v.y, v.z, v.w};
    __nv_bfloat16 hi[4], lo[4];
#pragma unroll
    for (int i = 0; i < 4; i++) {
        hi[i] = __float2bfloat16(vv[i]);
        lo[i] = __float2bfloat16(vv[i] - __bfloat162float(hi[i]));
    }
    __nv_bfloat162 h01, h23, l01, l23;
    h01.x = hi[0]; h01.y = hi[1]; h23.x = hi[2]; h23.y = hi[3];
    l01.x = lo[0]; l01.y = lo[1]; l23.x = lo[2]; l23.y = lo[3];
    *reinterpret_cast<__nv_bfloat162*>(dst + e)     = h01;
    *reinterpret_cast<__nv_bfloat162*>(dst + e + 2) = h23;
    if (which == 0) {
        *reinterpret_cast<__nv_bfloat162*>(dst + 256 + e)     = h01;
        *reinterpret_cast<__nv_bfloat162*>(dst + 256 + e + 2) = h23;
        *reinterpret_cast<__nv_bfloat162*>(dst + 512 + e)     = l01;
        *reinterpret_cast<__nv_bfloat162*>(dst + 512 + e + 2) = l23;
    } else {
        *reinterpret_cast<__nv_bfloat162*>(dst + 256 + e)     = l01;
        *reinterpret_cast<__nv_bfloat162*>(dst + 256 + e + 2) = l23;
        *reinterpret_cast<__nv_bfloat162*>(dst + 512 + e)     = h01;
        *reinterpret_cast<__nv_bfloat162*>(dst + 512 + e + 2) = h23;
    }
}

__global__ void uot_norm_pack_kernel(const float* __restrict__ f1,
                                     const float* __restrict__ f2) {
    int gwa  = (blockIdx.x * blockDim.x + threadIdx.x) >> 5;   // 0..65535
    int lane = threadIdx.x & 31;
    int which = (gwa >= Bdim * Nn) ? 1 : 0;
    int gw = which ? (gwa - Bdim * Nn) : gwa;
    const float* src = which ? f2 : f1;

    const float4* s4 = reinterpret_cast<const float4*>(src) + (size_t)gw * 64;
    float4 v0 = s4[lane];
    float4 v1 = s4[lane + 32];
    float ss = v0.x*v0.x + v0.y*v0.y + v0.z*v0.z + v0.w*v0.w
             + v1.x*v1.x + v1.y*v1.y + v1.z*v1.z + v1.w*v1.w;
    ss = warp_sum(ss);
    float inv = 1.0f / sqrtf(ss + 1e-8f);
    v0.x *= inv; v0.y *= inv; v0.z *= inv; v0.w *= inv;
    v1.x *= inv; v1.y *= inv; v1.z *= inv; v1.w *= inv;

    __nv_bfloat16* dst = (which ? g_f2p : g_f1p) + (size_t)gw * KPACK;
    int e = lane * 4;
    pack_store(dst, e, v0, which);
    pack_store(dst, e + 128, v1, which);
}

// ---------------------------------------------------------------------------
// 2. HMMA GEMM: Ks = 2^41*exp((f1.f2-1)/eps), fp16 store,
//    PLUS fused init colsum: per-tile 128-row column sums -> g_part[b][ry][c].
// ---------------------------------------------------------------------------
#define STAGE_BYTES 16384                 // 128 rows x 128 B
#define BUF_BYTES   32768                 // A + B per stage
#define SMEM_DYN    98304                 // 3 bufs

__global__ __launch_bounds__(256) void uot_mma_exp_kernel() {
    extern __shared__ char smem[];
    uint32_t sb = smem_u32(smem);
    int tid  = threadIdx.x;
    int wid  = tid >> 5;
    int lane = tid & 31;

    int bz = blockIdx.z;
    int r0 = blockIdx.y * 128;     // output rows  (f1 index)
    int c0 = blockIdx.x * 128;     // output cols  (f2 index)

    const char* Abase = reinterpret_cast<const char*>(
        g_f1p + ((size_t)bz * Nn + r0) * KPACK);
    const char* Bbase = reinterpret_cast<const char*>(
        g_f2p + ((size_t)bz * Mm + c0) * KPACK);

    int segid[8];
#pragma unroll
    for (int i = 0; i < 8; i++) segid[i] = tid + i * 256;

    auto prefetch = [&](int st) {
        uint32_t base = sb + (uint32_t)(st % 3) * BUF_BYTES;
        const char* Asrc = Abase + st * 128;
        const char* Bsrc = Bbase + st * 128;
#pragma unroll
        for (int i = 0; i < 8; i++) {
            int l   = segid[i];
            int isB = l >> 10;
            int row = (l >> 3) & 127;
            int seg = l & 7;
            const char* src = (isB ? Bsrc : Asrc) + (size_t)row * (KPACK * 2) + seg * 16;
            uint32_t dst = base + isB * STAGE_BYTES + SWZ128(row * 128 + seg * 16);
            cp_async16(dst, src);
        }
    };

    int mt = (wid & 3) * 32;        // warp row offset (A side)
    int ntw = (wid >> 2) * 64;      // warp col offset (B side)

    int arow0 = mt + (lane & 15);
    int aks   = lane >> 4;
    uint32_t aoff0 = arow0 * 128;
    uint32_t axor0 = (uint32_t)((arow0 & 7) * 16);
    int arow1 = arow0 + 16;
    uint32_t aoff1 = arow1 * 128;
    uint32_t axor1 = (uint32_t)((arow1 & 7) * 16);

    int brow = ntw + ((lane & 7) | ((lane >> 1) & 8));
    int bks  = (lane >> 3) & 1;
    uint32_t boff = brow * 128;
    uint32_t bxor = (uint32_t)((brow & 7) * 16);

    float acc[2][8][4];
#pragma unroll
    for (int i = 0; i < 2; i++)
#pragma unroll
        for (int j = 0; j < 8; j++)
#pragma unroll
            for (int k = 0; k < 4; k++) acc[i][j][k] = 0.0f;

    prefetch(0); CP_COMMIT();
    prefetch(1); CP_COMMIT();

    for (int st = 0; st < 12; st++) {
        CP_WAIT(1);
        __syncthreads();
        if (st + 2 < 12) { prefetch(st + 2); CP_COMMIT(); }

        uint32_t baseA = sb + (uint32_t)(st % 3) * BUF_BYTES;
        uint32_t baseB = baseA + STAGE_BYTES;
#pragma unroll
        for (int kc = 0; kc < 4; kc++) {
            uint32_t kseg = (uint32_t)((kc * 2 + aks) * 16);
            uint32_t a0[4], a1[4];
            ldsm_x4(a0, baseA + aoff0 + (kseg ^ axor0));
            ldsm_x4(a1, baseA + aoff1 + (kseg ^ axor1));
            uint32_t kbseg = (uint32_t)((kc * 2 + bks) * 16);
#pragma unroll
            for (int nb = 0; nb < 4; nb++) {
                uint32_t bfrag[4];
                ldsm_x4(bfrag, baseB + boff + (uint32_t)(nb * 16 * 128) + (kbseg ^ bxor));
                mma_bf16(acc[0][2 * nb + 0], a0, bfrag[0], bfrag[1]);
                mma_bf16(acc[0][2 * nb + 1], a0, bfrag[2], bfrag[3]);
                mma_bf16(acc[1][2 * nb + 0], a1, bfrag[0], bfrag[1]);
                mma_bf16(acc[1][2 * nb + 1], a1, bfrag[2], bfrag[3]);
            }
        }
    }
    __syncthreads();   // all ldsm reads done before smem reuse below

    // --- Epilogue: exp -> fp16 store + per-tile column sums ---
    int g  = lane >> 2;
    int tg = lane & 3;
    __half* Kout = g_K + ((size_t)bz * Nn + r0) * Mm + c0;
    float cs[8][2];
#pragma unroll
    for (int ni = 0; ni < 8; ni++) { cs[ni][0] = 0.f; cs[ni][1] = 0.f; }
#pragma unroll
    for (int mi = 0; mi < 2; mi++) {
        int rowA = mt + mi * 16 + g;
#pragma unroll
        for (int ni = 0; ni < 8; ni++) {
            int col = ntw + ni * 8 + tg * 2;
            float* d = acc[mi][ni];
            float e0 = fminf(__expf(fmaf(d[0] - 1.0f, INV_EPS, LN_SCALE)), 60000.0f);
            float e1 = fminf(__expf(fmaf(d[1] - 1.0f, INV_EPS, LN_SCALE)), 60000.0f);
            float e2 = fminf(__expf(fmaf(d[2] - 1.0f, INV_EPS, LN_SCALE)), 60000.0f);
            float e3 = fminf(__expf(fmaf(d[3] - 1.0f, INV_EPS, LN_SCALE)), 60000.0f);
            *reinterpret_cast<__half2*>(&Kout[(size_t)rowA * Mm + col]) =
                __floats2half2_rn(e0, e1);
            *reinterpret_cast<__half2*>(&Kout[(size_t)(rowA + 8) * Mm + col]) =
                __floats2half2_rn(e2, e3);
            cs[ni][0] += e0 + e2;
            cs[ni][1] += e1 + e3;
        }
    }
    // reduce over the 8 g-lanes (same tg): shfl_xor 4/8/16 flips g bits
    float* csm = reinterpret_cast<float*>(smem);   // 8 warps x 64 cols
#pragma unroll
    for (int ni = 0; ni < 8; ni++) {
#pragma unroll
        for (int k = 0; k < 2; k++) {
            float v = cs[ni][k];
            v += __shfl_xor_sync(0xffffffffu, v, 4);
            v += __shfl_xor_sync(0xffffffffu, v, 8);
            v += __shfl_xor_sync(0xffffffffu, v, 16);
            if (g == 0) csm[wid * 64 + ni * 8 + tg * 2 + k] = v;
        }
    }
    __syncthreads();
    if (tid < 128) {
        int c = tid;
        float s = (c < 64)
            ? csm[0 * 64 + c] + csm[1 * 64 + c] + csm[2 * 64 + c] + csm[3 * 64 + c]
            : csm[4 * 64 + (c - 64)] + csm[5 * 64 + (c - 64)]
            + csm[6 * 64 + (c - 64)] + csm[7 * 64 + (c - 64)];
        g_part[((size_t)(bz * 32) + blockIdx.y) * Mm + c0 + c] = s;
    }
}

// ---------------------------------------------------------------------------
// 3. b = (prob2*S / (scale * sum of cnt partials + 1e-8*S)) ^ power
// ---------------------------------------------------------------------------
__global__ void uot_b_update_kernel(int cnt, float scale) {
    int i = blockIdx.x * blockDim.x + threadIdx.x;
    if (i >= Bdim * Mm) return;
    int b = i >> 12;
    int m = i & 4095;
    const float* p = g_part + (size_t)(b * 32) * Mm + m;
    float s = 0.f;
    for (int j = 0; j < cnt; j++) s += p[(size_t)j * Mm];
    g_b[i] = powf(PROB_S / (s * scale + REG_S), POWER);
}

// ---------------------------------------------------------------------------
// 4. Fused Sinkhorn pass (4096 blocks, 512 threads, 75% occupancy):
//    Block = 8 rows x 4096 cols. Phase a: TWO warps per row (half-row dots),
//    staging rows to smem. Phase b: each thread owns one 16B segment (8 cols),
//    colsum over 8 rows from smem (conflict-free).
// ---------------------------------------------------------------------------
#define FUSED_ROWS 8
#define FUSED_SMEM (FUSED_ROWS * Mm * 2 + 128)     // 65664

__global__ __launch_bounds__(512, 3) void uot_fused_kernel() {
    extern __shared__ char fsm[];
    __half* tile    = reinterpret_cast<__half*>(fsm);              // 8 x 4096 halves
    float*  sh_half = reinterpret_cast<float*>(fsm + FUSED_ROWS * Mm * 2);  // 16
    float*  sh_a    = sh_half + 16;                                          // 8
    int tid  = threadIdx.x;
    int wid  = tid >> 5;               // 0..15
    int lane = tid & 31;
    int rb = blockIdx.x;               // 0..511
    int b  = blockIdx.y;               // 0..7
    int row0 = rb * FUSED_ROWS;
    const __half* Kbase = g_K + ((size_t)b * Nn + row0) * Mm;
    const float4* bp = reinterpret_cast<const float4*>(g_b + b * Mm);

    // phase a: warp wid handles row wid>>1, half wid&1 (2048 cols)
    {
        int r = wid >> 1, h = wid & 1;
        const uint4*  Kp  = reinterpret_cast<const uint4*>(Kbase + (size_t)r * Mm + h * 2048);
        uint4*        Tp  = reinterpret_cast<uint4*>(tile + (size_t)r * Mm + h * 2048);
        const float4* bph = bp + h * 512;
        float acc = 0.f;
#pragma unroll
        for (int it = 0; it < 8; it++) {
            int idx = it * 32 + lane;
            uint4 u = Kp[idx];
            Tp[idx] = u;
            float2 f0 = __half22float2(*reinterpret_cast<__half2*>(&u.x));
            float2 f1 = __half22float2(*reinterpret_cast<__half2*>(&u.y));
            float2 f2 = __half22float2(*reinterpret_cast<__half2*>(&u.z));
            float2 f3 = __half22float2(*reinterpret_cast<__half2*>(&u.w));
            float4 b0 = __ldg(&bph[idx * 2]);
            float4 b1 = __ldg(&bph[idx * 2 + 1]);
            acc += f0.x * b0.x + f0.y * b0.y + f1.x * b0.z + f1.y * b0.w
                 + f2.x * b1.x + f2.y * b1.y + f3.x * b1.z + f3.y * b1.w;
        }
        acc = warp_sum(acc);
        if (lane == 0) sh_half[wid] = acc;
    }
    __syncthreads();
    if (tid < FUSED_ROWS)
        sh_a[tid] = powf(PROB_S / (sh_half[2 * tid] + sh_half[2 * tid + 1] + REG_S), POWER);
    __syncthreads();

    // phase b: thread owns 16B segment tid (cols tid*8 .. +7)
    float ca[8];
#pragma unroll
    for (int j = 0; j < 8; j++) ca[j] = 0.f;
#pragma unroll
    for (int r = 0; r < FUSED_ROWS; r++) {
        uint4 u = reinterpret_cast<const uint4*>(tile + (size_t)r * Mm)[tid];
        float a = sh_a[r];
        float2 f;
        f = __half22float2(*reinterpret_cast<__half2*>(&u.x)); ca[0] = fmaf(a, f.x, ca[0]); ca[1] = fmaf(a, f.y, ca[1]);
        f = __half22float2(*reinterpret_cast<__half2*>(&u.y)); ca[2] = fmaf(a, f.x, ca[2]); ca[3] = fmaf(a, f.y, ca[3]);
        f = __half22float2(*reinterpret_cast<__half2*>(&u.z)); ca[4] = fmaf(a, f.x, ca[4]); ca[5] = fmaf(a, f.y, ca[5]);
        f = __half22float2(*reinterpret_cast<__half2*>(&u.w)); ca[6] = fmaf(a, f.x, ca[6]); ca[7] = fmaf(a, f.y, ca[7]);
    }
    float* prow = g_part2 + ((size_t)(b * 512 + rb)) * Mm + tid * 8;
    reinterpret_cast<float4*>(prow)[0] = make_float4(ca[0], ca[1], ca[2], ca[3]);
    reinterpret_cast<float4*>(prow)[1] = make_float4(ca[4], ca[5], ca[6], ca[7]);
}

// ---------------------------------------------------------------------------
// 5. Reduce 512 fused partials -> 8 level-1 partials (1024 blocks, full BW)
// ---------------------------------------------------------------------------
__global__ void uot_reduce_kernel() {
    int m = blockIdx.x * 256 + threadIdx.x;   // 0..4095
    int j = blockIdx.y;                        // 0..7
    int b = blockIdx.z;
    const float* p = g_part2 + ((size_t)(b * 512 + j * 64)) * Mm + m;
    float s0 = 0.f, s1 = 0.f, s2 = 0.f, s3 = 0.f;
#pragma unroll 4
    for (int t = 0; t < 64; t += 4) {
        s0 += p[(size_t)(t + 0) * Mm];
        s1 += p[(size_t)(t + 1) * Mm];
        s2 += p[(size_t)(t + 2) * Mm];
        s3 += p[(size_t)(t + 3) * Mm];
    }
    g_part[(size_t)(b * 32 + j) * Mm + m] = (s0 + s1) + (s2 + s3);
}

// ---------------------------------------------------------------------------
// 6. Final fused pass: Ks·b and Ks·(b*p2_{xyz}) -> a, w, corr
// ---------------------------------------------------------------------------
__global__ void uot_rowsum_final_kernel(const float* __restrict__ p2) {
    int gw   = (blockIdx.x * blockDim.x + threadIdx.x) >> 5;
    int lane = threadIdx.x & 31;
    if (gw >= Bdim * Nn) return;
    int b = gw >> 12;
    int n = gw & 4095;
    const uint4*  Kp  = reinterpret_cast<const uint4*>(g_K + ((size_t)b * Nn + n) * Mm);
    const float4* bp  = reinterpret_cast<const float4*>(g_b + b * Mm);
    const float*  p2b = p2 + (size_t)b * Mm * 3;

    float a0 = 0.f, ax = 0.f, ay = 0.f, az = 0.f;
    for (int it = 0; it < 16; it++) {
        int idx = it * 32 + lane;
        int m8  = idx * 8;
        uint4 u = Kp[idx];
        float kv[8];
        {
            float2 f0 = __half22float2(*reinterpret_cast<__half2*>(&u.x));
            float2 f1 = __half22float2(*reinterpret_cast<__half2*>(&u.y));
            float2 f2 = __half22float2(*reinterpret_cast<__half2*>(&u.z));
            float2 f3 = __half22float2(*reinterpret_cast<__half2*>(&u.w));
            kv[0] = f0.x; kv[1] = f0.y; kv[2] = f1.x; kv[3] = f1.y;
            kv[4] = f2.x; kv[5] = f2.y; kv[6] = f3.x; kv[7] = f3.y;
        }
        float bv[8];
        {
            float4 b0 = __ldg(&bp[idx * 2]);
            float4 b1 = __ldg(&bp[idx * 2 + 1]);
            bv[0] = b0.x; bv[1] = b0.y; bv[2] = b0.z; bv[3] = b0.w;
            bv[4] = b1.x; bv[5] = b1.y; bv[6] = b1.z; bv[7] = b1.w;
        }
        float pv[24];
        {
            const float4* q4 = reinterpret_cast<const float4*>(p2b + (size_t)m8 * 3);
#pragma unroll
            for (int t = 0; t < 6; t++) {
                float4 qq = __ldg(&q4[t]);
                pv[4 * t + 0] = qq.x; pv[4 * t + 1] = qq.y;
                pv[4 * t + 2] = qq.z; pv[4 * t + 3] = qq.w;
            }
        }
#pragma unroll
        for (int e = 0; e < 8; e++) {
            float t = kv[e] * bv[e];
            a0 += t;
            ax = fmaf(t, pv[e * 3 + 0], ax);
            ay = fmaf(t, pv[e * 3 + 1], ay);
            az = fmaf(t, pv[e * 3 + 2], az);
        }
    }
    a0 = warp_sum(a0);
    ax = warp_sum(ax);
    ay = warp_sum(ay);
    az = warp_sum(az);
    if (lane == 0) {
        float av  = powf(PROB_S / (a0 + REG_S), POWER);
        float kb  = a0 * INV_SCALE;
        float w   = av * kb;
        float inv = 1.0f / (w + 1e-8f);
        g_w[gw] = w;
        g_corr[(size_t)gw * 3 + 0] = av * (ax * INV_SCALE) * inv;
        g_corr[(size_t)gw * 3 + 1] = av * (ay * INV_SCALE) * inv;
        g_corr[(size_t)gw * 3 + 2] = av * (az * INV_SCALE) * inv;
    }
}

// ---------------------------------------------------------------------------
// 7. Weighted Kabsch, one block per batch. 3x3 SVD via Jacobi (double) on t0.
// ---------------------------------------------------------------------------
__global__ void uot_kabsch_kernel(const float* __restrict__ p1, float* __restrict__ out) {
    int b    = blockIdx.x;
    int tid  = threadIdx.x;
    int lane = tid & 31;
    int wid  = tid >> 5;

    __shared__ float red[8][16];
    __shared__ float sh[16];

    float v[7];
#pragma unroll
    for (int j = 0; j < 7; j++) v[j] = 0.f;
    for (int n = tid; n < Nn; n += 256) {
        float wv = g_w[b * Nn + n];
        const float* q1 = p1 + ((size_t)b * Nn + n) * 3;
        const float* qc = g_corr + ((size_t)b * Nn + n) * 3;
        v[0] += wv;
        v[1] += wv * q1[0]; v[2] += wv * q1[1]; v[3] += wv * q1[2];
        v[4] += wv * qc[0]; v[5] += wv * qc[1]; v[6] += wv * qc[2];
    }
#pragma unroll
    for (int j = 0; j < 7; j++) {
        float t = warp_sum(v[j]);
        if (lane == 0) red[wid][j] = t;
    }
    __syncthreads();
    if (tid < 7) {
        float t = 0.f;
        for (int w8 = 0; w8 < 8; w8++) t += red[w8][tid];
        sh[tid] = t;
    }
    __syncthreads();
    float denom = sh[0] + 1e-5f;
    float ca0 = sh[1] / denom, ca1 = sh[2] / denom, ca2 = sh[3] / denom;
    float cb0 = sh[4] / denom, cb1 = sh[5] / denom, cb2 = sh[6] / denom;
    __syncthreads();

    float c9[9];
#pragma unroll
    for (int j = 0; j < 9; j++) c9[j] = 0.f;
    for (int n = tid; n < Nn; n += 256) {
        float wn = g_w[b * Nn + n] / denom;
        const float* q1 = p1 + ((size_t)b * Nn + n) * 3;
        const float* qc = g_corr + ((size_t)b * Nn + n) * 3;
        float a0 = q1[0] - ca0, a1 = q1[1] - ca1, a2 = q1[2] - ca2;
        float e0 = (qc[0] - cb0) * wn, e1 = (qc[1] - cb1) * wn, e2 = (qc[2] - cb2) * wn;
        c9[0] += a0 * e0; c9[1] += a0 * e1; c9[2] += a0 * e2;
        c9[3] += a1 * e0; c9[4] += a1 * e1; c9[5] += a1 * e2;
        c9[6] += a2 * e0; c9[7] += a2 * e1; c9[8] += a2 * e2;
    }
#pragma unroll
    for (int j = 0; j < 9; j++) {
        float t = warp_sum(c9[j]);
        if (lane == 0) red[wid][j] = t;
    }
    __syncthreads();
    if (tid < 9) {
        float t = 0.f;
        for (int w8 = 0; w8 < 8; w8++) t += red[w8][tid];
        sh[tid] = t;
    }
    __syncthreads();

    if (tid == 0) {
        double Cv[3][3];
        for (int r = 0; r < 3; r++)
            for (int c = 0; c < 3; c++) Cv[r][c] = (double)sh[r * 3 + c];

        double S[3][3];
        for (int i = 0; i < 3; i++)
            for (int j = 0; j < 3; j++)
                S[i][j] = Cv[0][i] * Cv[0][j] + Cv[1][i] * Cv[1][j] + Cv[2][i] * Cv[2][j];

        double V[3][3] = {{1, 0, 0}, {0, 1, 0}, {0, 0, 1}};
        const int PQ[3][2] = {{0, 1}, {0, 2}, {1, 2}};
        for (int sweep = 0; sweep < 45; sweep++) {
            int p = PQ[sweep % 3][0], q = PQ[sweep % 3][1];
            double apq = S[p][q];
            if (fabs(apq) < 1e-60) continue;
            double tau = (S[q][q] - S[p][p]) / (2.0 * apq);
            double t   = ((tau >= 0.0) ? 1.0 : -1.0) / (fabs(tau) + sqrt(1.0 + tau * tau));
            double cc  = 1.0 / sqrt(1.0 + t * t);
            double ss  = t * cc;
            for (int k = 0; k < 3; k++) {
                double skp = S[k][p], skq = S[k][q];
                S[k][p] = cc * skp - ss * skq;
                S[k][q] = ss * skp + cc * skq;
            }
            for (int k = 0; k < 3; k++) {
                double spk = S[p][k], sqk = S[q][k];
                S[p][k] = cc * spk - ss * sqk;
                S[q][k] = ss * spk + cc * sqk;
            }
            for (int k = 0; k < 3; k++) {
                double vkp = V[k][p], vkq = V[k][q];
                V[k][p] = cc * vkp - ss * vkq;
                V[k][q] = ss * vkp + cc * vkq;
            }
        }

        double lam[3] = {S[0][0], S[1][1], S[2][2]};
        int idx[3] = {0, 1, 2};
        for (int i = 0; i < 2; i++)
            for (int j = i + 1; j < 3; j++)
                if (lam[idx[j]] > lam[idx[i]]) { int t = idx[i]; idx[i] = idx[j]; idx[j] = t; }

        double Vs[3][3];
        for (int r = 0; r < 3; r++)
            for (int i = 0; i < 3; i++) Vs[r][i] = V[r][idx[i]];

        double U[3][3];
        for (int i = 0; i < 3; i++)
            for (int r = 0; r < 3; r++)
                U[r][i] = Cv[r][0] * Vs[0][i] + Cv[r][1] * Vs[1][i] + Cv[r][2] * Vs[2][i];

        {
            double nrm = sqrt(U[0][0]*U[0][0] + U[1][0]*U[1][0] + U[2][0]*U[2][0]);
            double inv = (nrm > 1e-150) ? 1.0 / nrm : 0.0;
            for (int r = 0; r < 3; r++) U[r][0] *= inv;
        }
        {
            double d01 = U[0][0]*U[0][1] + U[1][0]*U[1][1] + U[2][0]*U[2][1];
            for (int r = 0; r < 3; r++) U[r][1] -= d01 * U[r][0];
            double nrm = sqrt(U[0][1]*U[0][1] + U[1][1]*U[1][1] + U[2][1]*U[2][1]);
            double inv = (nrm > 1e-150) ? 1.0 / nrm : 0.0;
            for (int r = 0; r < 3; r++) U[r][1] *= inv;
        }
        {
            double d02 = U[0][0]*U[0][2] + U[1][0]*U[1][2] + U[2][0]*U[2][2];
            double d12 = U[0][1]*U[0][2] + U[1][1]*U[1][2] + U[2][1]*U[2][2];
            for (int r = 0; r < 3; r++) U[r][2] -= d02 * U[r][0] + d12 * U[r][1];
            double nrm = sqrt(U[0][2]*U[0][2] + U[1][2]*U[1][2] + U[2][2]*U[2][2]);
            if (nrm > 1e-12) {
                for (int r = 0; r < 3; r++) U[r][2] /= nrm;
            } else {
                U[0][2] = U[1][0]*U[2][1] - U[2][0]*U[1][1];
                U[1][2] = U[2][0]*U[0][1] - U[0][0]*U[2][1];
                U[2][2] = U[0][0]*U[1][1] - U[1][0]*U[0][1];
            }
        }

        double R[3][3];
        for (int r = 0; r < 3; r++)
            for (int c = 0; c < 3; c++)
                R[r][c] = Vs[r][0]*U[c][0] + Vs[r][1]*U[c][1] + Vs[r][2]*U[c][2];
        double det = R[0][0]*(R[1][1]*R[2][2] - R[1][2]*R[2][1])
                   - R[0][1]*(R[1][0]*R[2][2] - R[1][2]*R[2][0])
                   + R[0][2]*(R[1][0]*R[2][1] - R[1][1]*R[2][0]);
        if (!(det > 0.0)) {
            for (int r = 0; r < 3; r++)
                for (int c = 0; c < 3; c++)
                    R[r][c] -= 2.0 * Vs[r][2] * U[c][2];
        }

        double cad[3] = {ca0, ca1, ca2};
        double cbd[3] = {cb0, cb1, cb2};
        for (int r = 0; r < 3; r++) {
            double tr = cbd[r] - (R[r][0]*cad[0] + R[r][1]*cad[1] + R[r][2]*cad[2]);
            out[b * 12 + r * 4 + 0] = (float)R[r][0];
            out[b * 12 + r * 4 + 1] = (float)R[r][1];
            out[b * 12 + r * 4 + 2] = (float)R[r][2];
            out[b * 12 + r * 4 + 3] = (float)tr;
        }
    }
}

// ---------------------------------------------------------------------------
// Launch
// ---------------------------------------------------------------------------
extern "C" void kernel_launch(void* const* d_in, const int* in_sizes, int n_in,
                              void* d_out, int out_size) {
    const float* f1 = (const float*)d_in[0];
    const float* f2 = (const float*)d_in[1];
    const float* p1 = (const float*)d_in[2];
    const float* p2 = (const float*)d_in[3];
    float* out = (float*)d_out;

    static bool attr_set = false;
    if (!attr_set) {
        cudaFuncSetAttribute(uot_mma_exp_kernel,
                             cudaFuncAttributeMaxDynamicSharedMemorySize, SMEM_DYN);
        cudaFuncSetAttribute(uot_fused_kernel,
                             cudaFuncAttributeMaxDynamicSharedMemorySize, FUSED_SMEM);
        attr_set = true;
    }

    uot_norm_pack_kernel<<<8192, 256>>>(f1, f2);
    // GEMM also produces init colsum partials (32 per batch) in g_part
    uot_mma_exp_kernel<<<dim3(32, 32, Bdim), 256, SMEM_DYN>>>();

    // iteration 1: b1 from GEMM-fused colsum (32 partials, scaled by a0=1/N)
    uot_b_update_kernel<<<(Bdim * Mm + 255) / 256, 256>>>(32, PROB);

    // iterations 1..9: fused rowsum->a_t (smem tile), colsum(a_t) -> b_{t+1}
    for (int it = 0; it < 9; ++it) {
        uot_fused_kernel<<<dim3(512, Bdim), 512, FUSED_SMEM>>>();
        uot_reduce_kernel<<<dim3(16, 8, Bdim), 256>>>();
        uot_b_update_kernel<<<(Bdim * Mm + 255) / 256, 256>>>(8, 1.0f);
    }

    // iteration 10's rowsum: a_10, w, corr (uses b_10)
    uot_rowsum_final_kernel<<<4096, 256>>>(p2);

    uot_kabsch_kernel<<<Bdim, 256>>>(p1, out);
}